// round 1
// baseline (speedup 1.0000x reference)
#include <cuda_runtime.h>
#include <cstdint>

// Problem constants (fixed by the dataset)
#define B_  8
#define T_  4096
#define D_  1024
#define H_  16
#define DH_ 64
#define UMAX 64      // u = 41 actual; arrays sized for <=64
#define TT  128      // attention K/V tile (time dimension)

// ---------------------------------------------------------------------------
// Scratch (device globals — no allocations allowed)
// ---------------------------------------------------------------------------
__device__ float g_K[(size_t)B_ * T_ * D_];        // 134 MB
__device__ float g_V[(size_t)B_ * T_ * D_];        // 134 MB
__device__ float g_Qs[B_ * UMAX * D_];             // gathered+projected queries
__device__ float g_ctx[B_ * UMAX * D_];            // attention context rows (y layout)
__device__ float g_mean[B_ * D_];                  // mean ctx per batch (y layout)
__device__ float g_yo_mean[B_ * D_];               // broadcast output row per batch
__device__ float g_yo_idx[B_ * UMAX * D_];         // output rows at idx positions
__device__ int   g_rowmap[B_ * UMAX];

// ---------------------------------------------------------------------------
// Generic fp32 GEMM: C[m,n] = sum_k X[row(m),k] * W[n,k] (+ bias[n])
// N is fixed at 1024 (= D_). BM=BN=128, BK=16, 256 threads, 8x8 register tile.
// rowmap != null -> gathered X rows (used for the Qs projection).
// ---------------------------------------------------------------------------
#define BM 128
#define BN 128
#define BK 16

__global__ __launch_bounds__(256)
void gemm_xwT(const float* __restrict__ X, const float* __restrict__ W,
              float* __restrict__ C, const int* __restrict__ rowmap,
              const float* __restrict__ bias, int M)
{
    __shared__ float Xs[BK][BM + 4];
    __shared__ float Ws[BK][BN + 4];

    const int tid = threadIdx.x;
    const int tr  = tid >> 4;      // 0..15
    const int tc  = tid & 15;      // 0..15
    const int bm  = blockIdx.y * BM;
    const int bn  = blockIdx.x * BN;

    float acc[8][8];
#pragma unroll
    for (int i = 0; i < 8; i++)
#pragma unroll
        for (int j = 0; j < 8; j++) acc[i][j] = 0.f;

    for (int k0 = 0; k0 < D_; k0 += BK) {
#pragma unroll
        for (int jj = 0; jj < 8; jj++) {
            int e = tid + jj * 256;       // 0..2047
            int r = e >> 4, c = e & 15;
            int gm = bm + r;
            float xv = 0.f;
            if (gm < M) {
                int sr = rowmap ? rowmap[gm] : gm;
                xv = X[(size_t)sr * D_ + k0 + c];
            }
            Xs[c][r] = xv;
            Ws[c][r] = W[(size_t)(bn + r) * D_ + k0 + c];
        }
        __syncthreads();
#pragma unroll
        for (int k = 0; k < BK; k++) {
            float xr[8], wr[8];
#pragma unroll
            for (int i = 0; i < 8; i++) xr[i] = Xs[k][tr * 8 + i];
#pragma unroll
            for (int j = 0; j < 8; j++) wr[j] = Ws[k][tc * 8 + j];
#pragma unroll
            for (int i = 0; i < 8; i++)
#pragma unroll
                for (int j = 0; j < 8; j++)
                    acc[i][j] += xr[i] * wr[j];
        }
        __syncthreads();
    }

#pragma unroll
    for (int i = 0; i < 8; i++) {
        int gm = bm + tr * 8 + i;
        if (gm >= M) continue;
#pragma unroll
        for (int j = 0; j < 8; j++) {
            int gn = bn + tc * 8 + j;
            float v = acc[i][j];
            if (bias) v += bias[gn];
            C[(size_t)gm * D_ + gn] = v;
        }
    }
}

// ---------------------------------------------------------------------------
// rowmap[b*u + iu] = b*T + idx[iu]
// ---------------------------------------------------------------------------
__global__ void build_rowmap(const int* __restrict__ idx, int* __restrict__ rowmap, int u)
{
    int i = blockIdx.x * blockDim.x + threadIdx.x;
    if (i < B_ * u) {
        int b = i / u, iu = i - b * u;
        rowmap[i] = b * T_ + idx[iu];
    }
}

// ---------------------------------------------------------------------------
// Flash attention: one CTA per (b,h). u queries x T keys, DH=64.
// ctx[(b*u+iu)*D + h*64 + d] and mean over iu into g_mean.
// ---------------------------------------------------------------------------
__global__ __launch_bounds__(256)
void attn_kernel(const float* __restrict__ Qs, const float* __restrict__ Kg,
                 const float* __restrict__ Vg, float* __restrict__ ctx,
                 float* __restrict__ meanv, int u)
{
    extern __shared__ float sm[];
    float* q    = sm;                        // UMAX*64
    float* KtT  = q + UMAX * 64;             // 64*(TT+1), transposed K tile
    float* Vt   = KtT + 64 * (TT + 1);       // TT*64
    float* S    = Vt + TT * 64;              // UMAX*TT
    float* accb = S + UMAX * TT;             // UMAX*64
    float* mrow = accb + UMAX * 64;          // UMAX
    float* lrow = mrow + UMAX;               // UMAX

    const int h = blockIdx.x, b = blockIdx.y;
    const int tid = threadIdx.x;
    const float scale = 0.125f;              // 1/sqrt(64)

    for (int e = tid; e < u * 64; e += 256) {
        int ur = e >> 6, c = e & 63;
        q[e]    = Qs[(size_t)(b * u + ur) * D_ + h * 64 + c];
        accb[e] = 0.f;
    }
    if (tid < UMAX) { mrow[tid] = -1e30f; lrow[tid] = 0.f; }
    __syncthreads();

    for (int t0 = 0; t0 < T_; t0 += TT) {
        // load K (transposed into smem) and V tiles, float4 from global
        for (int e = tid; e < TT * 16; e += 256) {
            int r = e >> 4, c4 = e & 15;
            size_t goff = (size_t)(b * T_ + t0 + r) * D_ + h * 64 + c4 * 4;
            float4 kv = *(const float4*)(Kg + goff);
            float4 vv = *(const float4*)(Vg + goff);
            KtT[(c4 * 4 + 0) * (TT + 1) + r] = kv.x;
            KtT[(c4 * 4 + 1) * (TT + 1) + r] = kv.y;
            KtT[(c4 * 4 + 2) * (TT + 1) + r] = kv.z;
            KtT[(c4 * 4 + 3) * (TT + 1) + r] = kv.w;
            *(float4*)(Vt + r * 64 + c4 * 4) = vv;
        }
        __syncthreads();

        // S[ur][tr] = scale * q[ur] . K[tr]   (conflict-free: K transposed)
        for (int e = tid; e < u * TT; e += 256) {
            int ur = e >> 7, tr = e & (TT - 1);
            const float* qr = q + ur * 64;
            float s = 0.f;
#pragma unroll
            for (int c = 0; c < 64; c++) s += qr[c] * KtT[c * (TT + 1) + tr];
            S[ur * TT + tr] = s * scale;
        }
        __syncthreads();

        // online softmax update, one warp per query row
        const int wid = tid >> 5, lane = tid & 31;
        for (int ur = wid; ur < u; ur += 8) {
            float mx = -1e30f;
#pragma unroll
            for (int tr = lane; tr < TT; tr += 32) mx = fmaxf(mx, S[ur * TT + tr]);
#pragma unroll
            for (int o = 16; o; o >>= 1) mx = fmaxf(mx, __shfl_xor_sync(0xffffffffu, mx, o));
            float mold = mrow[ur];
            float mnew = fmaxf(mold, mx);
            float corr = __expf(mold - mnew);
            float ls = 0.f;
#pragma unroll
            for (int tr = lane; tr < TT; tr += 32) {
                float p = __expf(S[ur * TT + tr] - mnew);
                S[ur * TT + tr] = p;
                ls += p;
            }
#pragma unroll
            for (int o = 16; o; o >>= 1) ls += __shfl_xor_sync(0xffffffffu, ls, o);
#pragma unroll
            for (int d = lane; d < 64; d += 32) accb[ur * 64 + d] *= corr;
            if (lane == 0) { mrow[ur] = mnew; lrow[ur] = lrow[ur] * corr + ls; }
        }
        __syncthreads();

        // acc += P @ V  (S row broadcast, V coalesced across lanes)
        for (int e = tid; e < u * 64; e += 256) {
            int ur = e >> 6, d = e & 63;
            const float* Sr = S + ur * TT;
            const float* Vd = Vt + d;
            float s = 0.f;
#pragma unroll 8
            for (int tr = 0; tr < TT; tr++) s += Sr[tr] * Vd[tr * 64];
            accb[e] += s;
        }
        __syncthreads();
    }

    // ctx rows
    for (int e = tid; e < u * 64; e += 256) {
        int ur = e >> 6;
        ctx[(size_t)(b * u + ur) * D_ + h * 64 + (e & 63)] = accb[e] / lrow[ur];
    }
    __syncthreads();
    // mean over queries for this (b,h)
    if (tid < 64) {
        float s = 0.f;
        for (int ur = 0; ur < u; ur++) s += accb[ur * 64 + tid] / lrow[ur];
        meanv[b * D_ + h * 64 + tid] = s / (float)u;
    }
}

// ---------------------------------------------------------------------------
// out[b,t,:] = yo_mean[b,:] for all t (float4), then scatter idx rows
// ---------------------------------------------------------------------------
__global__ void broadcast_out(const float* __restrict__ yo_mean, float* __restrict__ out)
{
    size_t i = (size_t)blockIdx.x * blockDim.x + threadIdx.x;  // over B*T*(D/4)
    if (i >= (size_t)B_ * T_ * (D_ / 4)) return;
    int d4 = (int)(i & (D_ / 4 - 1));
    int b  = (int)(i >> 8) >> 12;   // i/(D/4)/T
    ((float4*)out)[i] = ((const float4*)yo_mean)[b * (D_ / 4) + d4];
}

__global__ void scatter_out(const float* __restrict__ yo_idx, const int* __restrict__ idx,
                            float* __restrict__ out, int u)
{
    int row = blockIdx.x;            // b*u + iu
    int b = row / u, iu = row - b * u;
    int t = idx[iu];
    const float4* src = (const float4*)(yo_idx + (size_t)row * D_);
    float4* dst = (float4*)(out + ((size_t)(b * T_ + t)) * D_);
    dst[threadIdx.x] = src[threadIdx.x];   // 256 threads x float4 = 1024 floats
}

// ---------------------------------------------------------------------------
// Launch
// ---------------------------------------------------------------------------
extern "C" void kernel_launch(void* const* d_in, const int* in_sizes, int n_in,
                              void* d_out, int out_size)
{
    const float* x  = (const float*)d_in[0];
    const float* Wq = (const float*)d_in[1];
    const float* Wk = (const float*)d_in[2];
    const float* Wv = (const float*)d_in[3];
    const float* Wo = (const float*)d_in[4];
    const float* bo = (const float*)d_in[5];
    const int*  idx = (const int*)d_in[6];
    const int u = in_sizes[6];
    float* out = (float*)d_out;

    float *pK, *pV, *pQs, *pctx, *pmean, *pyom, *pyoi;
    int* prm;
    cudaGetSymbolAddress((void**)&pK,    g_K);
    cudaGetSymbolAddress((void**)&pV,    g_V);
    cudaGetSymbolAddress((void**)&pQs,   g_Qs);
    cudaGetSymbolAddress((void**)&pctx,  g_ctx);
    cudaGetSymbolAddress((void**)&pmean, g_mean);
    cudaGetSymbolAddress((void**)&pyom,  g_yo_mean);
    cudaGetSymbolAddress((void**)&pyoi,  g_yo_idx);
    cudaGetSymbolAddress((void**)&prm,   g_rowmap);

    // 1. gather map for query rows
    build_rowmap<<<(B_ * u + 255) / 256, 256>>>(idx, prm, u);

    // 2. Qs = x[idx] @ Wq^T   (M = B*u)
    gemm_xwT<<<dim3(D_ / BN, (B_ * u + BM - 1) / BM), 256>>>(x, Wq, pQs, prm, nullptr, B_ * u);

    // 3/4. K = x @ Wk^T, V = x @ Wv^T   (M = B*T) — the FLOP-dominant GEMMs
    dim3 gkv(D_ / BN, (B_ * T_) / BM);
    gemm_xwT<<<gkv, 256>>>(x, Wk, pK, nullptr, nullptr, B_ * T_);
    gemm_xwT<<<gkv, 256>>>(x, Wv, pV, nullptr, nullptr, B_ * T_);

    // 5. flash attention per (b,h); also produces per-batch mean ctx
    const size_t smem_bytes = sizeof(float) *
        (UMAX * 64 + 64 * (TT + 1) + TT * 64 + UMAX * TT + UMAX * 64 + 2 * UMAX);
    cudaFuncSetAttribute((const void*)attn_kernel,
                         cudaFuncAttributeMaxDynamicSharedMemorySize, (int)smem_bytes);
    attn_kernel<<<dim3(H_, B_), 256, smem_bytes>>>(pQs, pK, pV, pctx, pmean, u);

    // 6. epilogue: rows through Wo (+bo)
    gemm_xwT<<<dim3(D_ / BN, (B_ * u + BM - 1) / BM), 256>>>(pctx, Wo, pyoi, nullptr, bo, B_ * u);
    gemm_xwT<<<dim3(D_ / BN, 1), 256>>>(pmean, Wo, pyom, nullptr, bo, B_);

    // 7. broadcast mean row everywhere, then overwrite idx rows
    size_t nvec = (size_t)B_ * T_ * (D_ / 4);
    broadcast_out<<<(unsigned)((nvec + 255) / 256), 256>>>(pyom, out);
    scatter_out<<<B_ * u, 256>>>(pyoi, idx, out, u);
}

// round 3
// speedup vs baseline: 1.8129x; 1.8129x over previous
#include <cuda_runtime.h>
#include <cuda_bf16.h>
#include <cstdint>

// Problem constants (fixed by the dataset)
#define B_  8
#define T_  4096
#define D_  1024
#define H_  16
#define DH_ 64
#define UMAX 64      // u = 41 actual; arrays sized for <=64
#define TT  128      // attention K/V tile (time dimension)

// ---------------------------------------------------------------------------
// Scratch (device globals — no allocations allowed)
// ---------------------------------------------------------------------------
__device__ float g_K[(size_t)B_ * T_ * D_];        // 134 MB
__device__ float g_V[(size_t)B_ * T_ * D_];        // 134 MB
__device__ float g_Qs[B_ * UMAX * D_];
__device__ float g_ctx[B_ * UMAX * D_];
__device__ float g_mean[B_ * D_];
__device__ float g_yo_mean[B_ * D_];
__device__ float g_yo_idx[B_ * UMAX * D_];
__device__ int   g_rowmap[B_ * UMAX];

// bf16 hi/lo splits for tensor-core GEMMs
__device__ __nv_bfloat16 g_Xhi[(size_t)B_ * T_ * D_];   // 64 MB
__device__ __nv_bfloat16 g_Xlo[(size_t)B_ * T_ * D_];   // 64 MB
__device__ __nv_bfloat16 g_Wkhi[D_ * D_];
__device__ __nv_bfloat16 g_Wklo[D_ * D_];
__device__ __nv_bfloat16 g_Wvhi[D_ * D_];
__device__ __nv_bfloat16 g_Wvlo[D_ * D_];

// ---------------------------------------------------------------------------
// PTX helpers (sm_80+ portable: mma.sync + ldmatrix + cp.async)
// ---------------------------------------------------------------------------
__device__ __forceinline__ uint32_t smem_u32(const void* p) {
    uint32_t a;
    asm("{ .reg .u64 t; cvta.to.shared.u64 t, %1; cvt.u32.u64 %0, t; }" : "=r"(a) : "l"(p));
    return a;
}
__device__ __forceinline__ void cp16(uint32_t sdst, const void* gsrc) {
    asm volatile("cp.async.cg.shared.global [%0], [%1], 16;" :: "r"(sdst), "l"(gsrc));
}
#define CP_COMMIT() asm volatile("cp.async.commit_group;" ::: "memory")
#define CP_WAIT1()  asm volatile("cp.async.wait_group 1;" ::: "memory")

__device__ __forceinline__ void ldsm_x4(uint32_t* r, uint32_t addr) {
    asm volatile("ldmatrix.sync.aligned.m8n8.x4.shared.b16 {%0,%1,%2,%3}, [%4];"
        : "=r"(r[0]), "=r"(r[1]), "=r"(r[2]), "=r"(r[3]) : "r"(addr));
}
__device__ __forceinline__ void ldsm_x2(uint32_t* r, uint32_t addr) {
    asm volatile("ldmatrix.sync.aligned.m8n8.x2.shared.b16 {%0,%1}, [%2];"
        : "=r"(r[0]), "=r"(r[1]) : "r"(addr));
}
__device__ __forceinline__ void mma16816(float* c, const uint32_t* a, const uint32_t* b) {
    asm volatile(
        "mma.sync.aligned.m16n8k16.row.col.f32.bf16.bf16.f32 "
        "{%0,%1,%2,%3}, {%4,%5,%6,%7}, {%8,%9}, {%0,%1,%2,%3};"
        : "+f"(c[0]), "+f"(c[1]), "+f"(c[2]), "+f"(c[3])
        : "r"(a[0]), "r"(a[1]), "r"(a[2]), "r"(a[3]), "r"(b[0]), "r"(b[1]));
}

// ---------------------------------------------------------------------------
// hi/lo bf16 split kernel (vectorized x4)
// ---------------------------------------------------------------------------
__global__ void split_hi_lo(const float* __restrict__ src,
                            __nv_bfloat16* __restrict__ hi,
                            __nv_bfloat16* __restrict__ lo, int n4)
{
    int i = blockIdx.x * blockDim.x + threadIdx.x;
    if (i >= n4) return;
    float4 v = ((const float4*)src)[i];
    __nv_bfloat16 h0 = __float2bfloat16(v.x);
    __nv_bfloat16 h1 = __float2bfloat16(v.y);
    __nv_bfloat16 h2 = __float2bfloat16(v.z);
    __nv_bfloat16 h3 = __float2bfloat16(v.w);
    __nv_bfloat16 l0 = __float2bfloat16(v.x - __bfloat162float(h0));
    __nv_bfloat16 l1 = __float2bfloat16(v.y - __bfloat162float(h1));
    __nv_bfloat16 l2 = __float2bfloat16(v.z - __bfloat162float(h2));
    __nv_bfloat16 l3 = __float2bfloat16(v.w - __bfloat162float(h3));
    ((__nv_bfloat162*)hi)[2 * i]     = __halves2bfloat162(h0, h1);
    ((__nv_bfloat162*)hi)[2 * i + 1] = __halves2bfloat162(h2, h3);
    ((__nv_bfloat162*)lo)[2 * i]     = __halves2bfloat162(l0, l1);
    ((__nv_bfloat162*)lo)[2 * i + 1] = __halves2bfloat162(l2, l3);
}

// ---------------------------------------------------------------------------
// Tensor-core GEMM (HMMA): C[m,n] = sum_k X[m,k]*W[n,k] in fp32 via 3-term
// bf16 split. BM=BN=128, BK=32, double-buffered cp.async.
// SMEM stage (40960 B): Ahi | Alo | Bhi | Blo, each 128 rows x 32 bf16,
// row stride padded to 80 B (conflict-free for ldmatrix, 16B-aligned).
// ---------------------------------------------------------------------------
#define PSTR  40                 // padded row stride in bf16 elems (80 B)
#define MATB  (128 * 80)         // 10240 B per matrix
#define STG   (4 * MATB)         // 40960 B per stage
#define GEMM_SMEM (2 * STG)

__device__ __forceinline__ void load_stage(
    uint32_t sdst,
    const __nv_bfloat16* __restrict__ Ahi, const __nv_bfloat16* __restrict__ Alo,
    const __nv_bfloat16* __restrict__ Bhi, const __nv_bfloat16* __restrict__ Blo,
    int bm, int bn, int k0, int tid)
{
#pragma unroll
    for (int m = 0; m < 4; m++) {
        const __nv_bfloat16* base = (m == 0) ? Ahi : (m == 1) ? Alo : (m == 2) ? Bhi : Blo;
        int rowbase = (m < 2) ? bm : bn;
#pragma unroll
        for (int j = 0; j < 2; j++) {
            int c = tid + j * 256;          // 0..511 chunks of 16B
            int row = c >> 2, c16 = c & 3;
            const __nv_bfloat16* src = base + ((size_t)(rowbase + row) << 10) + k0 + c16 * 8;
            uint32_t dst = sdst + m * MATB + row * 80 + c16 * 16;
            cp16(dst, src);
        }
    }
}

__global__ __launch_bounds__(256, 1)
void gemm_mma(const __nv_bfloat16* __restrict__ Ahi, const __nv_bfloat16* __restrict__ Alo,
              const __nv_bfloat16* __restrict__ Bhi, const __nv_bfloat16* __restrict__ Blo,
              float* __restrict__ C)
{
    extern __shared__ char smem[];
    const uint32_t sb = smem_u32(smem);
    const int tid = threadIdx.x;
    const int wid = tid >> 5, lane = tid & 31;
    const int bm = blockIdx.y * 128;
    const int bn = blockIdx.x * 128;
    const int wm = (wid >> 2) * 64;     // warp row: 0 / 64
    const int wn = (wid & 3) * 32;      // warp col: 0/32/64/96

    float acc[4][4][4];
#pragma unroll
    for (int mi = 0; mi < 4; mi++)
#pragma unroll
        for (int ni = 0; ni < 4; ni++)
#pragma unroll
            for (int r = 0; r < 4; r++) acc[mi][ni][r] = 0.f;

    load_stage(sb,       Ahi, Alo, Bhi, Blo, bm, bn, 0,  tid); CP_COMMIT();
    load_stage(sb + STG, Ahi, Alo, Bhi, Blo, bm, bn, 32, tid); CP_COMMIT();

    const int l16 = lane & 15;
    const int arow = l16;
    const int acolb = (lane >> 4) * 8;
    const int brow = l16 & 7;
    const int bcolb = (l16 >> 3) * 8;

    for (int kt = 0; kt < 32; kt++) {
        uint32_t ss = sb + (kt & 1) * STG;
        CP_WAIT1();
        __syncthreads();

#pragma unroll
        for (int ks = 0; ks < 2; ks++) {
            uint32_t ah[4][4], al[4][4], bh[4][2], bl[4][2];
            const int acol = acolb + ks * 16;
            const int bcol = bcolb + ks * 16;
#pragma unroll
            for (int mi = 0; mi < 4; mi++) {
                uint32_t ao = ss + ((wm + mi * 16 + arow) * PSTR + acol) * 2;
                ldsm_x4(ah[mi], ao);
                ldsm_x4(al[mi], ao + MATB);
            }
#pragma unroll
            for (int ni = 0; ni < 4; ni++) {
                uint32_t bo = ss + 2 * MATB + ((wn + ni * 8 + brow) * PSTR + bcol) * 2;
                ldsm_x2(bh[ni], bo);
                ldsm_x2(bl[ni], bo + MATB);
            }
#pragma unroll
            for (int mi = 0; mi < 4; mi++)
#pragma unroll
                for (int ni = 0; ni < 4; ni++) {
                    mma16816(acc[mi][ni], ah[mi], bh[ni]);
                    mma16816(acc[mi][ni], ah[mi], bl[ni]);
                    mma16816(acc[mi][ni], al[mi], bh[ni]);
                }
        }
        __syncthreads();
        if (kt + 2 < 32)
            load_stage(ss, Ahi, Alo, Bhi, Blo, bm, bn, (kt + 2) * 32, tid);
        CP_COMMIT();           // exactly one group per iteration
    }

    // epilogue: write fp32 accumulators
    const int r0 = lane >> 2, c0 = (lane & 3) * 2;
#pragma unroll
    for (int mi = 0; mi < 4; mi++)
#pragma unroll
        for (int ni = 0; ni < 4; ni++) {
            int gr = bm + wm + mi * 16 + r0;
            int gc = bn + wn + ni * 8 + c0;
            float2 v0; v0.x = acc[mi][ni][0]; v0.y = acc[mi][ni][1];
            float2 v1; v1.x = acc[mi][ni][2]; v1.y = acc[mi][ni][3];
            *(float2*)(C + (size_t)gr * D_ + gc) = v0;
            *(float2*)(C + (size_t)(gr + 8) * D_ + gc) = v1;
        }
}

// ---------------------------------------------------------------------------
// fp32 SIMT GEMM (small M cases): C[m,n] = sum_k X[row(m),k]*W[n,k] (+bias)
// ---------------------------------------------------------------------------
#define BM 128
#define BN 128
#define BK 16

__global__ __launch_bounds__(256)
void gemm_xwT(const float* __restrict__ X, const float* __restrict__ W,
              float* __restrict__ C, const int* __restrict__ rowmap,
              const float* __restrict__ bias, int M)
{
    __shared__ float Xs[BK][BM + 4];
    __shared__ float Ws[BK][BN + 4];

    const int tid = threadIdx.x;
    const int tr  = tid >> 4;
    const int tc  = tid & 15;
    const int bm  = blockIdx.y * BM;
    const int bn  = blockIdx.x * BN;

    float acc[8][8];
#pragma unroll
    for (int i = 0; i < 8; i++)
#pragma unroll
        for (int j = 0; j < 8; j++) acc[i][j] = 0.f;

    for (int k0 = 0; k0 < D_; k0 += BK) {
#pragma unroll
        for (int jj = 0; jj < 8; jj++) {
            int e = tid + jj * 256;
            int r = e >> 4, c = e & 15;
            int gm = bm + r;
            float xv = 0.f;
            if (gm < M) {
                int sr = rowmap ? rowmap[gm] : gm;
                xv = X[(size_t)sr * D_ + k0 + c];
            }
            Xs[c][r] = xv;
            Ws[c][r] = W[(size_t)(bn + r) * D_ + k0 + c];
        }
        __syncthreads();
#pragma unroll
        for (int k = 0; k < BK; k++) {
            float xr[8], wr[8];
#pragma unroll
            for (int i = 0; i < 8; i++) xr[i] = Xs[k][tr * 8 + i];
#pragma unroll
            for (int j = 0; j < 8; j++) wr[j] = Ws[k][tc * 8 + j];
#pragma unroll
            for (int i = 0; i < 8; i++)
#pragma unroll
                for (int j = 0; j < 8; j++)
                    acc[i][j] += xr[i] * wr[j];
        }
        __syncthreads();
    }

#pragma unroll
    for (int i = 0; i < 8; i++) {
        int gm = bm + tr * 8 + i;
        if (gm >= M) continue;
#pragma unroll
        for (int j = 0; j < 8; j++) {
            int gn = bn + tc * 8 + j;
            float v = acc[i][j];
            if (bias) v += bias[gn];
            C[(size_t)gm * D_ + gn] = v;
        }
    }
}

// ---------------------------------------------------------------------------
__global__ void build_rowmap(const int* __restrict__ idx, int* __restrict__ rowmap, int u)
{
    int i = blockIdx.x * blockDim.x + threadIdx.x;
    if (i < B_ * u) {
        int b = i / u, iu = i - b * u;
        rowmap[i] = b * T_ + idx[iu];
    }
}

// ---------------------------------------------------------------------------
// Flash attention: one CTA per (b,h). u queries x T keys, DH=64.
// ---------------------------------------------------------------------------
__global__ __launch_bounds__(256)
void attn_kernel(const float* __restrict__ Qs, const float* __restrict__ Kg,
                 const float* __restrict__ Vg, float* __restrict__ ctx,
                 float* __restrict__ meanv, int u)
{
    extern __shared__ float sm[];
    float* q    = sm;
    float* KtT  = q + UMAX * 64;
    float* Vt   = KtT + 64 * (TT + 1);
    float* S    = Vt + TT * 64;
    float* accb = S + UMAX * TT;
    float* mrow = accb + UMAX * 64;
    float* lrow = mrow + UMAX;

    const int h = blockIdx.x, b = blockIdx.y;
    const int tid = threadIdx.x;
    const float scale = 0.125f;

    for (int e = tid; e < u * 64; e += 256) {
        int ur = e >> 6, c = e & 63;
        q[e]    = Qs[(size_t)(b * u + ur) * D_ + h * 64 + c];
        accb[e] = 0.f;
    }
    if (tid < UMAX) { mrow[tid] = -1e30f; lrow[tid] = 0.f; }
    __syncthreads();

    for (int t0 = 0; t0 < T_; t0 += TT) {
        for (int e = tid; e < TT * 16; e += 256) {
            int r = e >> 4, c4 = e & 15;
            size_t goff = (size_t)(b * T_ + t0 + r) * D_ + h * 64 + c4 * 4;
            float4 kv = *(const float4*)(Kg + goff);
            float4 vv = *(const float4*)(Vg + goff);
            KtT[(c4 * 4 + 0) * (TT + 1) + r] = kv.x;
            KtT[(c4 * 4 + 1) * (TT + 1) + r] = kv.y;
            KtT[(c4 * 4 + 2) * (TT + 1) + r] = kv.z;
            KtT[(c4 * 4 + 3) * (TT + 1) + r] = kv.w;
            *(float4*)(Vt + r * 64 + c4 * 4) = vv;
        }
        __syncthreads();

        for (int e = tid; e < u * TT; e += 256) {
            int ur = e >> 7, tr = e & (TT - 1);
            const float* qr = q + ur * 64;
            float s = 0.f;
#pragma unroll
            for (int c = 0; c < 64; c++) s += qr[c] * KtT[c * (TT + 1) + tr];
            S[ur * TT + tr] = s * scale;
        }
        __syncthreads();

        const int wid = tid >> 5, lane = tid & 31;
        for (int ur = wid; ur < u; ur += 8) {
            float mx = -1e30f;
#pragma unroll
            for (int tr = lane; tr < TT; tr += 32) mx = fmaxf(mx, S[ur * TT + tr]);
#pragma unroll
            for (int o = 16; o; o >>= 1) mx = fmaxf(mx, __shfl_xor_sync(0xffffffffu, mx, o));
            float mold = mrow[ur];
            float mnew = fmaxf(mold, mx);
            float corr = __expf(mold - mnew);
            float ls = 0.f;
#pragma unroll
            for (int tr = lane; tr < TT; tr += 32) {
                float p = __expf(S[ur * TT + tr] - mnew);
                S[ur * TT + tr] = p;
                ls += p;
            }
#pragma unroll
            for (int o = 16; o; o >>= 1) ls += __shfl_xor_sync(0xffffffffu, ls, o);
#pragma unroll
            for (int d = lane; d < 64; d += 32) accb[ur * 64 + d] *= corr;
            if (lane == 0) { mrow[ur] = mnew; lrow[ur] = lrow[ur] * corr + ls; }
        }
        __syncthreads();

        for (int e = tid; e < u * 64; e += 256) {
            int ur = e >> 6, d = e & 63;
            const float* Sr = S + ur * TT;
            const float* Vd = Vt + d;
            float s = 0.f;
#pragma unroll 8
            for (int tr = 0; tr < TT; tr++) s += Sr[tr] * Vd[tr * 64];
            accb[e] += s;
        }
        __syncthreads();
    }

    for (int e = tid; e < u * 64; e += 256) {
        int ur = e >> 6;
        ctx[(size_t)(b * u + ur) * D_ + h * 64 + (e & 63)] = accb[e] / lrow[ur];
    }
    __syncthreads();
    if (tid < 64) {
        float s = 0.f;
        for (int ur = 0; ur < u; ur++) s += accb[ur * 64 + tid] / lrow[ur];
        meanv[b * D_ + h * 64 + tid] = s / (float)u;
    }
}

// ---------------------------------------------------------------------------
__global__ void broadcast_out(const float* __restrict__ yo_mean, float* __restrict__ out)
{
    size_t i = (size_t)blockIdx.x * blockDim.x + threadIdx.x;
    if (i >= (size_t)B_ * T_ * (D_ / 4)) return;
    int d4 = (int)(i & (D_ / 4 - 1));
    int b  = (int)(i >> 8) >> 12;
    ((float4*)out)[i] = ((const float4*)yo_mean)[b * (D_ / 4) + d4];
}

__global__ void scatter_out(const float* __restrict__ yo_idx, const int* __restrict__ idx,
                            float* __restrict__ out, int u)
{
    int row = blockIdx.x;
    int b = row / u, iu = row - b * u;
    int t = idx[iu];
    const float4* src = (const float4*)(yo_idx + (size_t)row * D_);
    float4* dst = (float4*)(out + ((size_t)(b * T_ + t)) * D_);
    dst[threadIdx.x] = src[threadIdx.x];
}

// ---------------------------------------------------------------------------
// Launch
// ---------------------------------------------------------------------------
extern "C" void kernel_launch(void* const* d_in, const int* in_sizes, int n_in,
                              void* d_out, int out_size)
{
    const float* x  = (const float*)d_in[0];
    const float* Wq = (const float*)d_in[1];
    const float* Wk = (const float*)d_in[2];
    const float* Wv = (const float*)d_in[3];
    const float* Wo = (const float*)d_in[4];
    const float* bo = (const float*)d_in[5];
    const int*  idx = (const int*)d_in[6];
    const int u = in_sizes[6];
    float* out = (float*)d_out;

    float *pK, *pV, *pQs, *pctx, *pmean, *pyom, *pyoi;
    int* prm;
    __nv_bfloat16 *pXhi, *pXlo, *pWkhi, *pWklo, *pWvhi, *pWvlo;
    cudaGetSymbolAddress((void**)&pK,    g_K);
    cudaGetSymbolAddress((void**)&pV,    g_V);
    cudaGetSymbolAddress((void**)&pQs,   g_Qs);
    cudaGetSymbolAddress((void**)&pctx,  g_ctx);
    cudaGetSymbolAddress((void**)&pmean, g_mean);
    cudaGetSymbolAddress((void**)&pyom,  g_yo_mean);
    cudaGetSymbolAddress((void**)&pyoi,  g_yo_idx);
    cudaGetSymbolAddress((void**)&prm,   g_rowmap);
    cudaGetSymbolAddress((void**)&pXhi,  g_Xhi);
    cudaGetSymbolAddress((void**)&pXlo,  g_Xlo);
    cudaGetSymbolAddress((void**)&pWkhi, g_Wkhi);
    cudaGetSymbolAddress((void**)&pWklo, g_Wklo);
    cudaGetSymbolAddress((void**)&pWvhi, g_Wvhi);
    cudaGetSymbolAddress((void**)&pWvlo, g_Wvlo);

    // 0. bf16 hi/lo splits
    {
        int n4x = (B_ * T_ * D_) / 4;
        split_hi_lo<<<(n4x + 255) / 256, 256>>>(x, pXhi, pXlo, n4x);
        int n4w = (D_ * D_) / 4;
        split_hi_lo<<<(n4w + 255) / 256, 256>>>(Wk, pWkhi, pWklo, n4w);
        split_hi_lo<<<(n4w + 255) / 256, 256>>>(Wv, pWvhi, pWvlo, n4w);
    }

    // 1. gather map for query rows
    build_rowmap<<<(B_ * u + 255) / 256, 256>>>(idx, prm, u);

    // 2. Qs = x[idx] @ Wq^T (small, fp32 SIMT)
    gemm_xwT<<<dim3(D_ / BN, (B_ * u + BM - 1) / BM), 256>>>(x, Wq, pQs, prm, nullptr, B_ * u);

    // 3/4. K = x @ Wk^T, V = x @ Wv^T — HMMA tensor cores (3-term bf16 split)
    cudaFuncSetAttribute((const void*)gemm_mma,
                         cudaFuncAttributeMaxDynamicSharedMemorySize, GEMM_SMEM);
    dim3 gkv(D_ / 128, (B_ * T_) / 128);
    gemm_mma<<<gkv, 256, GEMM_SMEM>>>(pXhi, pXlo, pWkhi, pWklo, pK);
    gemm_mma<<<gkv, 256, GEMM_SMEM>>>(pXhi, pXlo, pWvhi, pWvlo, pV);

    // 5. flash attention per (b,h)
    const size_t smem_bytes = sizeof(float) *
        (UMAX * 64 + 64 * (TT + 1) + TT * 64 + UMAX * TT + UMAX * 64 + 2 * UMAX);
    cudaFuncSetAttribute((const void*)attn_kernel,
                         cudaFuncAttributeMaxDynamicSharedMemorySize, (int)smem_bytes);
    attn_kernel<<<dim3(H_, B_), 256, smem_bytes>>>(pQs, pK, pV, pctx, pmean, u);

    // 6. epilogue: rows through Wo (+bo)
    gemm_xwT<<<dim3(D_ / BN, (B_ * u + BM - 1) / BM), 256>>>(pctx, Wo, pyoi, nullptr, bo, B_ * u);
    gemm_xwT<<<dim3(D_ / BN, 1), 256>>>(pmean, Wo, pyom, nullptr, bo, B_);

    // 7. broadcast mean row everywhere, then overwrite idx rows
    size_t nvec = (size_t)B_ * T_ * (D_ / 4);
    broadcast_out<<<(unsigned)((nvec + 255) / 256), 256>>>(pyom, out);
    scatter_out<<<B_ * u, 256>>>(pyoi, idx, out, u);
}

// round 4
// speedup vs baseline: 2.1257x; 1.1725x over previous
#include <cuda_runtime.h>
#include <cuda_bf16.h>
#include <cstdint>

// Problem constants (fixed by the dataset)
#define B_  8
#define T_  4096
#define D_  1024
#define H_  16
#define DH_ 64
#define UMAX 48      // u = 41 actual; attention pads to 48 (8 warps x 6 rows)
#define TT  128      // attention K/V tile (time dimension)

// ---------------------------------------------------------------------------
// Scratch (device globals — no allocations allowed)
// ---------------------------------------------------------------------------
__device__ float g_K[(size_t)B_ * T_ * D_];        // 134 MB
__device__ float g_V[(size_t)B_ * T_ * D_];        // 134 MB
__device__ float g_Qs[B_ * UMAX * D_];
__device__ float g_ctx[B_ * UMAX * D_];
__device__ float g_mean[B_ * D_];
__device__ float g_yo_mean[B_ * D_];
__device__ float g_yo_idx[B_ * UMAX * D_];
__device__ int   g_rowmap[B_ * UMAX];

// bf16 hi/lo splits for tensor-core GEMMs
__device__ __nv_bfloat16 g_Xhi[(size_t)B_ * T_ * D_];   // 64 MB
__device__ __nv_bfloat16 g_Xlo[(size_t)B_ * T_ * D_];   // 64 MB
__device__ __nv_bfloat16 g_Wkhi[D_ * D_];
__device__ __nv_bfloat16 g_Wklo[D_ * D_];
__device__ __nv_bfloat16 g_Wvhi[D_ * D_];
__device__ __nv_bfloat16 g_Wvlo[D_ * D_];

// ---------------------------------------------------------------------------
// PTX helpers (sm_80+ portable: mma.sync + ldmatrix + cp.async)
// ---------------------------------------------------------------------------
__device__ __forceinline__ uint32_t smem_u32(const void* p) {
    uint32_t a;
    asm("{ .reg .u64 t; cvta.to.shared.u64 t, %1; cvt.u32.u64 %0, t; }" : "=r"(a) : "l"(p));
    return a;
}
__device__ __forceinline__ void cp16(uint32_t sdst, const void* gsrc) {
    asm volatile("cp.async.cg.shared.global [%0], [%1], 16;" :: "r"(sdst), "l"(gsrc));
}
#define CP_COMMIT() asm volatile("cp.async.commit_group;" ::: "memory")
#define CP_WAIT1()  asm volatile("cp.async.wait_group 1;" ::: "memory")

__device__ __forceinline__ void ldsm_x4(uint32_t* r, uint32_t addr) {
    asm volatile("ldmatrix.sync.aligned.m8n8.x4.shared.b16 {%0,%1,%2,%3}, [%4];"
        : "=r"(r[0]), "=r"(r[1]), "=r"(r[2]), "=r"(r[3]) : "r"(addr));
}
__device__ __forceinline__ void ldsm_x2(uint32_t* r, uint32_t addr) {
    asm volatile("ldmatrix.sync.aligned.m8n8.x2.shared.b16 {%0,%1}, [%2];"
        : "=r"(r[0]), "=r"(r[1]) : "r"(addr));
}
__device__ __forceinline__ void mma16816(float* c, const uint32_t* a, const uint32_t* b) {
    asm volatile(
        "mma.sync.aligned.m16n8k16.row.col.f32.bf16.bf16.f32 "
        "{%0,%1,%2,%3}, {%4,%5,%6,%7}, {%8,%9}, {%0,%1,%2,%3};"
        : "+f"(c[0]), "+f"(c[1]), "+f"(c[2]), "+f"(c[3])
        : "r"(a[0]), "r"(a[1]), "r"(a[2]), "r"(a[3]), "r"(b[0]), "r"(b[1]));
}

// ---------------------------------------------------------------------------
// hi/lo bf16 split kernel (vectorized x4)
// ---------------------------------------------------------------------------
__global__ void split_hi_lo(const float* __restrict__ src,
                            __nv_bfloat16* __restrict__ hi,
                            __nv_bfloat16* __restrict__ lo, int n4)
{
    int i = blockIdx.x * blockDim.x + threadIdx.x;
    if (i >= n4) return;
    float4 v = ((const float4*)src)[i];
    __nv_bfloat16 h0 = __float2bfloat16(v.x);
    __nv_bfloat16 h1 = __float2bfloat16(v.y);
    __nv_bfloat16 h2 = __float2bfloat16(v.z);
    __nv_bfloat16 h3 = __float2bfloat16(v.w);
    __nv_bfloat16 l0 = __float2bfloat16(v.x - __bfloat162float(h0));
    __nv_bfloat16 l1 = __float2bfloat16(v.y - __bfloat162float(h1));
    __nv_bfloat16 l2 = __float2bfloat16(v.z - __bfloat162float(h2));
    __nv_bfloat16 l3 = __float2bfloat16(v.w - __bfloat162float(h3));
    ((__nv_bfloat162*)hi)[2 * i]     = __halves2bfloat162(h0, h1);
    ((__nv_bfloat162*)hi)[2 * i + 1] = __halves2bfloat162(h2, h3);
    ((__nv_bfloat162*)lo)[2 * i]     = __halves2bfloat162(l0, l1);
    ((__nv_bfloat162*)lo)[2 * i + 1] = __halves2bfloat162(l2, l3);
}

// ---------------------------------------------------------------------------
// Tensor-core GEMM (HMMA): C[m,n] = sum_k X[m,k]*W[n,k] in fp32 via 3-term
// bf16 split. BM=BN=128, BK=32, double-buffered cp.async.
// ---------------------------------------------------------------------------
#define PSTR  40                 // padded row stride in bf16 elems (80 B)
#define MATB  (128 * 80)         // 10240 B per matrix
#define STG   (4 * MATB)         // 40960 B per stage
#define GEMM_SMEM (2 * STG)

__device__ __forceinline__ void load_stage(
    uint32_t sdst,
    const __nv_bfloat16* __restrict__ Ahi, const __nv_bfloat16* __restrict__ Alo,
    const __nv_bfloat16* __restrict__ Bhi, const __nv_bfloat16* __restrict__ Blo,
    int bm, int bn, int k0, int tid)
{
#pragma unroll
    for (int m = 0; m < 4; m++) {
        const __nv_bfloat16* base = (m == 0) ? Ahi : (m == 1) ? Alo : (m == 2) ? Bhi : Blo;
        int rowbase = (m < 2) ? bm : bn;
#pragma unroll
        for (int j = 0; j < 2; j++) {
            int c = tid + j * 256;
            int row = c >> 2, c16 = c & 3;
            const __nv_bfloat16* src = base + ((size_t)(rowbase + row) << 10) + k0 + c16 * 8;
            uint32_t dst = sdst + m * MATB + row * 80 + c16 * 16;
            cp16(dst, src);
        }
    }
}

__global__ __launch_bounds__(256, 1)
void gemm_mma(const __nv_bfloat16* __restrict__ Ahi, const __nv_bfloat16* __restrict__ Alo,
              const __nv_bfloat16* __restrict__ Bhi, const __nv_bfloat16* __restrict__ Blo,
              float* __restrict__ C)
{
    extern __shared__ char smem[];
    const uint32_t sb = smem_u32(smem);
    const int tid = threadIdx.x;
    const int wid = tid >> 5, lane = tid & 31;
    const int bm = blockIdx.y * 128;
    const int bn = blockIdx.x * 128;
    const int wm = (wid >> 2) * 64;
    const int wn = (wid & 3) * 32;

    float acc[4][4][4];
#pragma unroll
    for (int mi = 0; mi < 4; mi++)
#pragma unroll
        for (int ni = 0; ni < 4; ni++)
#pragma unroll
            for (int r = 0; r < 4; r++) acc[mi][ni][r] = 0.f;

    load_stage(sb,       Ahi, Alo, Bhi, Blo, bm, bn, 0,  tid); CP_COMMIT();
    load_stage(sb + STG, Ahi, Alo, Bhi, Blo, bm, bn, 32, tid); CP_COMMIT();

    const int l16 = lane & 15;
    const int arow = l16;
    const int acolb = (lane >> 4) * 8;
    const int brow = l16 & 7;
    const int bcolb = (l16 >> 3) * 8;

    for (int kt = 0; kt < 32; kt++) {
        uint32_t ss = sb + (kt & 1) * STG;
        CP_WAIT1();
        __syncthreads();

#pragma unroll
        for (int ks = 0; ks < 2; ks++) {
            uint32_t ah[4][4], al[4][4], bh[4][2], bl[4][2];
            const int acol = acolb + ks * 16;
            const int bcol = bcolb + ks * 16;
#pragma unroll
            for (int mi = 0; mi < 4; mi++) {
                uint32_t ao = ss + ((wm + mi * 16 + arow) * PSTR + acol) * 2;
                ldsm_x4(ah[mi], ao);
                ldsm_x4(al[mi], ao + MATB);
            }
#pragma unroll
            for (int ni = 0; ni < 4; ni++) {
                uint32_t bo = ss + 2 * MATB + ((wn + ni * 8 + brow) * PSTR + bcol) * 2;
                ldsm_x2(bh[ni], bo);
                ldsm_x2(bl[ni], bo + MATB);
            }
#pragma unroll
            for (int mi = 0; mi < 4; mi++)
#pragma unroll
                for (int ni = 0; ni < 4; ni++) {
                    mma16816(acc[mi][ni], ah[mi], bh[ni]);
                    mma16816(acc[mi][ni], ah[mi], bl[ni]);
                    mma16816(acc[mi][ni], al[mi], bh[ni]);
                }
        }
        __syncthreads();
        if (kt + 2 < 32)
            load_stage(ss, Ahi, Alo, Bhi, Blo, bm, bn, (kt + 2) * 32, tid);
        CP_COMMIT();
    }

    const int r0 = lane >> 2, c0 = (lane & 3) * 2;
#pragma unroll
    for (int mi = 0; mi < 4; mi++)
#pragma unroll
        for (int ni = 0; ni < 4; ni++) {
            int gr = bm + wm + mi * 16 + r0;
            int gc = bn + wn + ni * 8 + c0;
            float2 v0; v0.x = acc[mi][ni][0]; v0.y = acc[mi][ni][1];
            float2 v1; v1.x = acc[mi][ni][2]; v1.y = acc[mi][ni][3];
            *(float2*)(C + (size_t)gr * D_ + gc) = v0;
            *(float2*)(C + (size_t)(gr + 8) * D_ + gc) = v1;
        }
}

// ---------------------------------------------------------------------------
// fp32 SIMT GEMM (small M cases): C[m,n] = sum_k X[row(m),k]*W[n,k] (+bias)
// ---------------------------------------------------------------------------
#define BM 128
#define BN 128
#define BK 16

__global__ __launch_bounds__(256)
void gemm_xwT(const float* __restrict__ X, const float* __restrict__ W,
              float* __restrict__ C, const int* __restrict__ rowmap,
              const float* __restrict__ bias, int M)
{
    __shared__ float Xs[BK][BM + 4];
    __shared__ float Ws[BK][BN + 4];

    const int tid = threadIdx.x;
    const int tr  = tid >> 4;
    const int tc  = tid & 15;
    const int bm  = blockIdx.y * BM;
    const int bn  = blockIdx.x * BN;

    float acc[8][8];
#pragma unroll
    for (int i = 0; i < 8; i++)
#pragma unroll
        for (int j = 0; j < 8; j++) acc[i][j] = 0.f;

    for (int k0 = 0; k0 < D_; k0 += BK) {
#pragma unroll
        for (int jj = 0; jj < 8; jj++) {
            int e = tid + jj * 256;
            int r = e >> 4, c = e & 15;
            int gm = bm + r;
            float xv = 0.f;
            if (gm < M) {
                int sr = rowmap ? rowmap[gm] : gm;
                xv = X[(size_t)sr * D_ + k0 + c];
            }
            Xs[c][r] = xv;
            Ws[c][r] = W[(size_t)(bn + r) * D_ + k0 + c];
        }
        __syncthreads();
#pragma unroll
        for (int k = 0; k < BK; k++) {
            float xr[8], wr[8];
#pragma unroll
            for (int i = 0; i < 8; i++) xr[i] = Xs[k][tr * 8 + i];
#pragma unroll
            for (int j = 0; j < 8; j++) wr[j] = Ws[k][tc * 8 + j];
#pragma unroll
            for (int i = 0; i < 8; i++)
#pragma unroll
                for (int j = 0; j < 8; j++)
                    acc[i][j] += xr[i] * wr[j];
        }
        __syncthreads();
    }

#pragma unroll
    for (int i = 0; i < 8; i++) {
        int gm = bm + tr * 8 + i;
        if (gm >= M) continue;
#pragma unroll
        for (int j = 0; j < 8; j++) {
            int gn = bn + tc * 8 + j;
            float v = acc[i][j];
            if (bias) v += bias[gn];
            C[(size_t)gm * D_ + gn] = v;
        }
    }
}

// ---------------------------------------------------------------------------
__global__ void build_rowmap(const int* __restrict__ idx, int* __restrict__ rowmap, int u)
{
    int i = blockIdx.x * blockDim.x + threadIdx.x;
    if (i < B_ * u) {
        int b = i / u, iu = i - b * u;
        rowmap[i] = b * T_ + idx[iu];
    }
}

// ---------------------------------------------------------------------------
// Flash attention, register-tiled. One CTA per (b,h); 8 warps x 6 query rows.
// Each lane owns 4 score cols (tr = 4*lane+k) and 2 output dims (lane, lane+32).
// Softmax stats in registers (warp shuffles); P staged once in smem.
// KStride = TT+4 = 132 floats (16B-aligned rows, conflict-free float4 reads).
// ---------------------------------------------------------------------------
#define KSTR 132

__global__ __launch_bounds__(256)
void attn_kernel(const float* __restrict__ Qs, const float* __restrict__ Kg,
                 const float* __restrict__ Vg, float* __restrict__ ctx,
                 float* __restrict__ meanv, int u)
{
    extern __shared__ float sm[];
    float* q    = sm;                      // 48*64
    float* KtT  = q + UMAX * 64;           // 64*KSTR
    float* Vt   = KtT + 64 * KSTR;         // TT*64
    float* P    = Vt + TT * 64;            // 48*TT
    float* msum = P + UMAX * TT;           // 64

    const int h = blockIdx.x, b = blockIdx.y;
    const int tid = threadIdx.x;
    const int wid = tid >> 5, lane = tid & 31;
    const int ur0 = wid * 6;

    // load q (pre-scaled by 1/sqrt(DH)); zero padded rows
    for (int e = tid; e < UMAX * 64; e += 256) {
        int ur = e >> 6, c = e & 63;
        q[e] = (ur < u) ? Qs[(size_t)(b * u + ur) * D_ + h * 64 + c] * 0.125f : 0.f;
    }
    if (tid < 64) msum[tid] = 0.f;

    float m_run[6], l_run[6], acc_o[6][2];
#pragma unroll
    for (int i = 0; i < 6; i++) {
        m_run[i] = -1e30f; l_run[i] = 0.f;
        acc_o[i][0] = 0.f; acc_o[i][1] = 0.f;
    }
    __syncthreads();

    for (int t0 = 0; t0 < T_; t0 += TT) {
        // load K transposed + V row-major
        for (int e = tid; e < TT * 16; e += 256) {
            int r = e >> 4, c4 = e & 15;
            size_t goff = (size_t)(b * T_ + t0 + r) * D_ + h * 64 + c4 * 4;
            float4 kv = *(const float4*)(Kg + goff);
            float4 vv = *(const float4*)(Vg + goff);
            KtT[(c4 * 4 + 0) * KSTR + r] = kv.x;
            KtT[(c4 * 4 + 1) * KSTR + r] = kv.y;
            KtT[(c4 * 4 + 2) * KSTR + r] = kv.z;
            KtT[(c4 * 4 + 3) * KSTR + r] = kv.w;
            *(float4*)(Vt + r * 64 + c4 * 4) = vv;
        }
        __syncthreads();

        // ---- QK^T: acc_s[6 rows][4 cols], cols tr = 4*lane + k
        float acc_s[6][4];
#pragma unroll
        for (int i = 0; i < 6; i++)
#pragma unroll
            for (int j = 0; j < 4; j++) acc_s[i][j] = 0.f;

        for (int c0 = 0; c0 < 64; c0 += 4) {
            float4 qv[6];
#pragma unroll
            for (int i = 0; i < 6; i++)
                qv[i] = *(const float4*)(q + (ur0 + i) * 64 + c0);
#pragma unroll
            for (int k = 0; k < 4; k++) {
                float4 kv = *(const float4*)(KtT + (c0 + k) * KSTR + lane * 4);
#pragma unroll
                for (int i = 0; i < 6; i++) {
                    float qs = (k == 0) ? qv[i].x : (k == 1) ? qv[i].y : (k == 2) ? qv[i].z : qv[i].w;
                    acc_s[i][0] += qs * kv.x;
                    acc_s[i][1] += qs * kv.y;
                    acc_s[i][2] += qs * kv.z;
                    acc_s[i][3] += qs * kv.w;
                }
            }
        }

        // ---- online softmax per row (warp-local)
#pragma unroll
        for (int i = 0; i < 6; i++) {
            float mx = fmaxf(fmaxf(acc_s[i][0], acc_s[i][1]), fmaxf(acc_s[i][2], acc_s[i][3]));
#pragma unroll
            for (int o = 16; o; o >>= 1) mx = fmaxf(mx, __shfl_xor_sync(0xffffffffu, mx, o));
            float mnew = fmaxf(m_run[i], mx);
            float corr = __expf(m_run[i] - mnew);
            float4 p;
            p.x = __expf(acc_s[i][0] - mnew);
            p.y = __expf(acc_s[i][1] - mnew);
            p.z = __expf(acc_s[i][2] - mnew);
            p.w = __expf(acc_s[i][3] - mnew);
            float ls = p.x + p.y + p.z + p.w;
#pragma unroll
            for (int o = 16; o; o >>= 1) ls += __shfl_xor_sync(0xffffffffu, ls, o);
            l_run[i] = l_run[i] * corr + ls;
            acc_o[i][0] *= corr;
            acc_o[i][1] *= corr;
            m_run[i] = mnew;
            *(float4*)(P + (ur0 + i) * TT + lane * 4) = p;
        }
        __syncwarp();

        // ---- PV: acc_o[6][2], dims d = lane, lane+32
        for (int t4 = 0; t4 < TT; t4 += 4) {
            float4 pv[6];
#pragma unroll
            for (int i = 0; i < 6; i++)
                pv[i] = *(const float4*)(P + (ur0 + i) * TT + t4);
#pragma unroll
            for (int k = 0; k < 4; k++) {
                float v0 = Vt[(t4 + k) * 64 + lane];
                float v1 = Vt[(t4 + k) * 64 + lane + 32];
#pragma unroll
                for (int i = 0; i < 6; i++) {
                    float pp = (k == 0) ? pv[i].x : (k == 1) ? pv[i].y : (k == 2) ? pv[i].z : pv[i].w;
                    acc_o[i][0] += pp * v0;
                    acc_o[i][1] += pp * v1;
                }
            }
        }
        __syncthreads();   // K/V/P consumed; safe to overwrite next tile
    }

    // ---- output + mean accumulation
#pragma unroll
    for (int i = 0; i < 6; i++) {
        int urg = ur0 + i;
        if (urg < u) {
            float inv = 1.f / l_run[i];
            float o0 = acc_o[i][0] * inv;
            float o1 = acc_o[i][1] * inv;
            size_t base = (size_t)(b * u + urg) * D_ + h * 64;
            ctx[base + lane]      = o0;
            ctx[base + lane + 32] = o1;
            atomicAdd(&msum[lane],      o0);
            atomicAdd(&msum[lane + 32], o1);
        }
    }
    __syncthreads();
    if (tid < 64) meanv[b * D_ + h * 64 + tid] = msum[tid] / (float)u;
}

// ---------------------------------------------------------------------------
__global__ void broadcast_out(const float* __restrict__ yo_mean, float* __restrict__ out)
{
    size_t i = (size_t)blockIdx.x * blockDim.x + threadIdx.x;
    if (i >= (size_t)B_ * T_ * (D_ / 4)) return;
    int d4 = (int)(i & (D_ / 4 - 1));
    int b  = (int)(i >> 8) >> 12;
    ((float4*)out)[i] = ((const float4*)yo_mean)[b * (D_ / 4) + d4];
}

__global__ void scatter_out(const float* __restrict__ yo_idx, const int* __restrict__ idx,
                            float* __restrict__ out, int u)
{
    int row = blockIdx.x;
    int b = row / u, iu = row - b * u;
    int t = idx[iu];
    const float4* src = (const float4*)(yo_idx + (size_t)row * D_);
    float4* dst = (float4*)(out + ((size_t)(b * T_ + t)) * D_);
    dst[threadIdx.x] = src[threadIdx.x];
}

// ---------------------------------------------------------------------------
// Launch
// ---------------------------------------------------------------------------
extern "C" void kernel_launch(void* const* d_in, const int* in_sizes, int n_in,
                              void* d_out, int out_size)
{
    const float* x  = (const float*)d_in[0];
    const float* Wq = (const float*)d_in[1];
    const float* Wk = (const float*)d_in[2];
    const float* Wv = (const float*)d_in[3];
    const float* Wo = (const float*)d_in[4];
    const float* bo = (const float*)d_in[5];
    const int*  idx = (const int*)d_in[6];
    const int u = in_sizes[6];
    float* out = (float*)d_out;

    float *pK, *pV, *pQs, *pctx, *pmean, *pyom, *pyoi;
    int* prm;
    __nv_bfloat16 *pXhi, *pXlo, *pWkhi, *pWklo, *pWvhi, *pWvlo;
    cudaGetSymbolAddress((void**)&pK,    g_K);
    cudaGetSymbolAddress((void**)&pV,    g_V);
    cudaGetSymbolAddress((void**)&pQs,   g_Qs);
    cudaGetSymbolAddress((void**)&pctx,  g_ctx);
    cudaGetSymbolAddress((void**)&pmean, g_mean);
    cudaGetSymbolAddress((void**)&pyom,  g_yo_mean);
    cudaGetSymbolAddress((void**)&pyoi,  g_yo_idx);
    cudaGetSymbolAddress((void**)&prm,   g_rowmap);
    cudaGetSymbolAddress((void**)&pXhi,  g_Xhi);
    cudaGetSymbolAddress((void**)&pXlo,  g_Xlo);
    cudaGetSymbolAddress((void**)&pWkhi, g_Wkhi);
    cudaGetSymbolAddress((void**)&pWklo, g_Wklo);
    cudaGetSymbolAddress((void**)&pWvhi, g_Wvhi);
    cudaGetSymbolAddress((void**)&pWvlo, g_Wvlo);

    // 0. bf16 hi/lo splits
    {
        int n4x = (B_ * T_ * D_) / 4;
        split_hi_lo<<<(n4x + 255) / 256, 256>>>(x, pXhi, pXlo, n4x);
        int n4w = (D_ * D_) / 4;
        split_hi_lo<<<(n4w + 255) / 256, 256>>>(Wk, pWkhi, pWklo, n4w);
        split_hi_lo<<<(n4w + 255) / 256, 256>>>(Wv, pWvhi, pWvlo, n4w);
    }

    // 1. gather map for query rows
    build_rowmap<<<(B_ * u + 255) / 256, 256>>>(idx, prm, u);

    // 2. Qs = x[idx] @ Wq^T (small, fp32 SIMT)
    gemm_xwT<<<dim3(D_ / BN, (B_ * u + BM - 1) / BM), 256>>>(x, Wq, pQs, prm, nullptr, B_ * u);

    // 3/4. K = x @ Wk^T, V = x @ Wv^T — HMMA tensor cores (3-term bf16 split)
    cudaFuncSetAttribute((const void*)gemm_mma,
                         cudaFuncAttributeMaxDynamicSharedMemorySize, GEMM_SMEM);
    dim3 gkv(D_ / 128, (B_ * T_) / 128);
    gemm_mma<<<gkv, 256, GEMM_SMEM>>>(pXhi, pXlo, pWkhi, pWklo, pK);
    gemm_mma<<<gkv, 256, GEMM_SMEM>>>(pXhi, pXlo, pWvhi, pWvlo, pV);

    // 5. flash attention per (b,h) — register-tiled
    const size_t smem_bytes = sizeof(float) *
        (UMAX * 64 + 64 * KSTR + TT * 64 + UMAX * TT + 64);
    cudaFuncSetAttribute((const void*)attn_kernel,
                         cudaFuncAttributeMaxDynamicSharedMemorySize, (int)smem_bytes);
    attn_kernel<<<dim3(H_, B_), 256, smem_bytes>>>(pQs, pK, pV, pctx, pmean, u);

    // 6. epilogue: rows through Wo (+bo)
    gemm_xwT<<<dim3(D_ / BN, (B_ * u + BM - 1) / BM), 256>>>(pctx, Wo, pyoi, nullptr, bo, B_ * u);
    gemm_xwT<<<dim3(D_ / BN, 1), 256>>>(pmean, Wo, pyom, nullptr, bo, B_);

    // 7. broadcast mean row everywhere, then overwrite idx rows
    size_t nvec = (size_t)B_ * T_ * (D_ / 4);
    broadcast_out<<<(unsigned)((nvec + 255) / 256), 256>>>(pyom, out);
    scatter_out<<<B_ * u, 256>>>(pyoi, idx, out, u);
}

// round 5
// speedup vs baseline: 2.7961x; 1.3154x over previous
#include <cuda_runtime.h>
#include <cuda_fp16.h>
#include <cstdint>

// Problem constants (fixed by the dataset)
#define B_  8
#define T_  4096
#define D_  1024
#define H_  16
#define DH_ 64
#define UMAX 48      // u = 41 actual; attention pads to 48 (8 warps x 6 rows)
#define TT  128      // attention K/V tile (time dimension)

// ---------------------------------------------------------------------------
// Scratch (device globals — no allocations allowed)
// ---------------------------------------------------------------------------
__device__ float g_K[(size_t)B_ * T_ * D_];        // 134 MB
__device__ float g_V[(size_t)B_ * T_ * D_];        // 134 MB
__device__ float g_Qs[B_ * UMAX * D_];
__device__ float g_ctx[B_ * UMAX * D_];
__device__ float g_mean[B_ * D_];
__device__ float g_yo_mean[B_ * D_];
__device__ float g_yo_idx[B_ * UMAX * D_];
__device__ int   g_rowmap[B_ * UMAX];

// fp16 planes for tensor-core GEMMs (x: hi+lo limbs; W: hi only)
__device__ __half g_Xh[(size_t)B_ * T_ * D_];      // 64 MB
__device__ __half g_Xl[(size_t)B_ * T_ * D_];      // 64 MB
__device__ __half g_Wkh[D_ * D_];
__device__ __half g_Wvh[D_ * D_];

// ---------------------------------------------------------------------------
// PTX helpers (sm_80+ portable: mma.sync + ldmatrix + cp.async)
// ---------------------------------------------------------------------------
__device__ __forceinline__ uint32_t smem_u32(const void* p) {
    uint32_t a;
    asm("{ .reg .u64 t; cvta.to.shared.u64 t, %1; cvt.u32.u64 %0, t; }" : "=r"(a) : "l"(p));
    return a;
}
__device__ __forceinline__ void cp16(uint32_t sdst, const void* gsrc) {
    asm volatile("cp.async.cg.shared.global [%0], [%1], 16;" :: "r"(sdst), "l"(gsrc));
}
#define CP_COMMIT() asm volatile("cp.async.commit_group;" ::: "memory")
#define CP_WAIT1()  asm volatile("cp.async.wait_group 1;" ::: "memory")

__device__ __forceinline__ void ldsm_x4(uint32_t* r, uint32_t addr) {
    asm volatile("ldmatrix.sync.aligned.m8n8.x4.shared.b16 {%0,%1,%2,%3}, [%4];"
        : "=r"(r[0]), "=r"(r[1]), "=r"(r[2]), "=r"(r[3]) : "r"(addr));
}
__device__ __forceinline__ void mma16816f16(float* c, const uint32_t* a, const uint32_t* b) {
    asm volatile(
        "mma.sync.aligned.m16n8k16.row.col.f32.f16.f16.f32 "
        "{%0,%1,%2,%3}, {%4,%5,%6,%7}, {%8,%9}, {%0,%1,%2,%3};"
        : "+f"(c[0]), "+f"(c[1]), "+f"(c[2]), "+f"(c[3])
        : "r"(a[0]), "r"(a[1]), "r"(a[2]), "r"(a[3]), "r"(b[0]), "r"(b[1]));
}

// ---------------------------------------------------------------------------
// prep kernels: fp16 hi/lo split for x, fp16 convert for W
// ---------------------------------------------------------------------------
__global__ void split_f16_hl(const float* __restrict__ src,
                             __half* __restrict__ hi, __half* __restrict__ lo, int n4)
{
    int i = blockIdx.x * blockDim.x + threadIdx.x;
    if (i >= n4) return;
    float4 v = ((const float4*)src)[i];
    __half h0 = __float2half(v.x), h1 = __float2half(v.y);
    __half h2 = __float2half(v.z), h3 = __float2half(v.w);
    __half l0 = __float2half(v.x - __half2float(h0));
    __half l1 = __float2half(v.y - __half2float(h1));
    __half l2 = __float2half(v.z - __half2float(h2));
    __half l3 = __float2half(v.w - __half2float(h3));
    ((__half2*)hi)[2 * i]     = __halves2half2(h0, h1);
    ((__half2*)hi)[2 * i + 1] = __halves2half2(h2, h3);
    ((__half2*)lo)[2 * i]     = __halves2half2(l0, l1);
    ((__half2*)lo)[2 * i + 1] = __halves2half2(l2, l3);
}

__global__ void conv_f16(const float* __restrict__ src, __half* __restrict__ dst, int n4)
{
    int i = blockIdx.x * blockDim.x + threadIdx.x;
    if (i >= n4) return;
    float4 v = ((const float4*)src)[i];
    ((__half2*)dst)[2 * i]     = __halves2half2(__float2half(v.x), __float2half(v.y));
    ((__half2*)dst)[2 * i + 1] = __halves2half2(__float2half(v.z), __float2half(v.w));
}

// ---------------------------------------------------------------------------
// Fused K+V tensor-core GEMM (fp16 2-term):
//   K[m,n] = sum_k (Xh+Xl)[m,k] * Wkh[n,k]
//   V[m,n] = sum_k (Xh+Xl)[m,k] * Wvh[n,k]
// 512 threads: warps 0-7 -> K tile, warps 8-15 -> V tile (shared A stages).
// BM=BN=128, BK=32, double-buffered cp.async.
// Stage (40960 B): Xh | Xl | Bk | Bv, each 128 rows x 32 f16, row stride 80 B.
// ---------------------------------------------------------------------------
#define PSTR  40                 // padded row stride in f16 elems (80 B)
#define MATB  (128 * 80)         // 10240 B per matrix
#define STG   (4 * MATB)         // 40960 B per stage
#define GEMM_SMEM (2 * STG)

__device__ __forceinline__ void load_stage(
    uint32_t sdst,
    const __half* __restrict__ Xh, const __half* __restrict__ Xl,
    const __half* __restrict__ Bk, const __half* __restrict__ Bv,
    int bm, int bn, int k0, int tid)
{
#pragma unroll
    for (int m = 0; m < 4; m++) {
        const __half* base = (m == 0) ? Xh : (m == 1) ? Xl : (m == 2) ? Bk : Bv;
        int rowbase = (m < 2) ? bm : bn;
        int c = tid;                     // 0..511 chunks of 16B
        int row = c >> 2, c16 = c & 3;
        const __half* src = base + ((size_t)(rowbase + row) << 10) + k0 + c16 * 8;
        uint32_t dst = sdst + m * MATB + row * 80 + c16 * 16;
        cp16(dst, src);
    }
}

__global__ __launch_bounds__(512, 1)
void gemm_fused(const __half* __restrict__ Xh, const __half* __restrict__ Xl,
                const __half* __restrict__ Bk, const __half* __restrict__ Bv,
                float* __restrict__ Ck, float* __restrict__ Cv)
{
    extern __shared__ char smem[];
    const uint32_t sb = smem_u32(smem);
    const int tid = threadIdx.x;
    const int wid = tid >> 5, lane = tid & 31;
    const int isV = wid >> 3;           // 0: K, 1: V
    const int ww  = wid & 7;
    const int bm = blockIdx.y * 128;
    const int bn = blockIdx.x * 128;
    const int wm = (ww >> 2) * 64;
    const int wn = (ww & 3) * 32;

    float acc[4][4][4];
#pragma unroll
    for (int mi = 0; mi < 4; mi++)
#pragma unroll
        for (int ni = 0; ni < 4; ni++)
#pragma unroll
            for (int r = 0; r < 4; r++) acc[mi][ni][r] = 0.f;

    load_stage(sb,       Xh, Xl, Bk, Bv, bm, bn, 0,  tid); CP_COMMIT();
    load_stage(sb + STG, Xh, Xl, Bk, Bv, bm, bn, 32, tid); CP_COMMIT();

    // ldmatrix lane addressing
    const int l16 = lane & 15;
    const int arow = l16;                  // A: 16 rows
    const int acolb = (lane >> 4) * 8;     // A: col half
    const int bg = lane >> 3;              // B x4: 4 groups of 8 lanes
    const int brow8 = lane & 7;
    const uint32_t boff = (2 + isV) * MATB;

    for (int kt = 0; kt < 32; kt++) {
        uint32_t ss = sb + (kt & 1) * STG;
        CP_WAIT1();
        __syncthreads();

#pragma unroll
        for (int ks = 0; ks < 2; ks++) {
            uint32_t ah[4][4], al[4][4], b[4][2];
            const int acol = acolb + ks * 16;
#pragma unroll
            for (int mi = 0; mi < 4; mi++) {
                uint32_t ao = ss + ((wm + mi * 16 + arow) * PSTR + acol) * 2;
                ldsm_x4(ah[mi], ao);
                ldsm_x4(al[mi], ao + MATB);
            }
            // B: two ldsm_x4, each covering 2 n-tiles x 2 col-halves
#pragma unroll
            for (int nip = 0; nip < 2; nip++) {
                int brr = wn + (2 * nip + (bg >> 1)) * 8 + brow8;
                int bcc = (bg & 1) * 8 + ks * 16;
                uint32_t r4[4];
                ldsm_x4(r4, ss + boff + (brr * PSTR + bcc) * 2);
                b[2 * nip][0] = r4[0]; b[2 * nip][1] = r4[1];
                b[2 * nip + 1][0] = r4[2]; b[2 * nip + 1][1] = r4[3];
            }
#pragma unroll
            for (int mi = 0; mi < 4; mi++)
#pragma unroll
                for (int ni = 0; ni < 4; ni++) {
                    mma16816f16(acc[mi][ni], ah[mi], b[ni]);
                    mma16816f16(acc[mi][ni], al[mi], b[ni]);
                }
        }
        __syncthreads();
        if (kt + 2 < 32)
            load_stage(ss, Xh, Xl, Bk, Bv, bm, bn, (kt + 2) * 32, tid);
        CP_COMMIT();
    }

    float* C = isV ? Cv : Ck;
    const int r0 = lane >> 2, c0 = (lane & 3) * 2;
#pragma unroll
    for (int mi = 0; mi < 4; mi++)
#pragma unroll
        for (int ni = 0; ni < 4; ni++) {
            int gr = bm + wm + mi * 16 + r0;
            int gc = bn + wn + ni * 8 + c0;
            float2 v0; v0.x = acc[mi][ni][0]; v0.y = acc[mi][ni][1];
            float2 v1; v1.x = acc[mi][ni][2]; v1.y = acc[mi][ni][3];
            *(float2*)(C + (size_t)gr * D_ + gc) = v0;
            *(float2*)(C + (size_t)(gr + 8) * D_ + gc) = v1;
        }
}

// ---------------------------------------------------------------------------
// fp32 SIMT GEMM (small M cases): C[m,n] = sum_k X[row(m),k]*W[n,k] (+bias)
// ---------------------------------------------------------------------------
#define BM 128
#define BN 128
#define BK 16

__global__ __launch_bounds__(256)
void gemm_xwT(const float* __restrict__ X, const float* __restrict__ W,
              float* __restrict__ C, const int* __restrict__ rowmap,
              const float* __restrict__ bias, int M)
{
    __shared__ float Xs[BK][BM + 4];
    __shared__ float Ws[BK][BN + 4];

    const int tid = threadIdx.x;
    const int tr  = tid >> 4;
    const int tc  = tid & 15;
    const int bm  = blockIdx.y * BM;
    const int bn  = blockIdx.x * BN;

    float acc[8][8];
#pragma unroll
    for (int i = 0; i < 8; i++)
#pragma unroll
        for (int j = 0; j < 8; j++) acc[i][j] = 0.f;

    for (int k0 = 0; k0 < D_; k0 += BK) {
#pragma unroll
        for (int jj = 0; jj < 8; jj++) {
            int e = tid + jj * 256;
            int r = e >> 4, c = e & 15;
            int gm = bm + r;
            float xv = 0.f;
            if (gm < M) {
                int sr = rowmap ? rowmap[gm] : gm;
                xv = X[(size_t)sr * D_ + k0 + c];
            }
            Xs[c][r] = xv;
            Ws[c][r] = W[(size_t)(bn + r) * D_ + k0 + c];
        }
        __syncthreads();
#pragma unroll
        for (int k = 0; k < BK; k++) {
            float xr[8], wr[8];
#pragma unroll
            for (int i = 0; i < 8; i++) xr[i] = Xs[k][tr * 8 + i];
#pragma unroll
            for (int j = 0; j < 8; j++) wr[j] = Ws[k][tc * 8 + j];
#pragma unroll
            for (int i = 0; i < 8; i++)
#pragma unroll
                for (int j = 0; j < 8; j++)
                    acc[i][j] += xr[i] * wr[j];
        }
        __syncthreads();
    }

#pragma unroll
    for (int i = 0; i < 8; i++) {
        int gm = bm + tr * 8 + i;
        if (gm >= M) continue;
#pragma unroll
        for (int j = 0; j < 8; j++) {
            int gn = bn + tc * 8 + j;
            float v = acc[i][j];
            if (bias) v += bias[gn];
            C[(size_t)gm * D_ + gn] = v;
        }
    }
}

// ---------------------------------------------------------------------------
__global__ void build_rowmap(const int* __restrict__ idx, int* __restrict__ rowmap, int u)
{
    int i = blockIdx.x * blockDim.x + threadIdx.x;
    if (i < B_ * u) {
        int b = i / u, iu = i - b * u;
        rowmap[i] = b * T_ + idx[iu];
    }
}

// ---------------------------------------------------------------------------
// Flash attention, register-tiled. One CTA per (b,h); 8 warps x 6 query rows.
// ---------------------------------------------------------------------------
#define KSTR 132

__global__ __launch_bounds__(256)
void attn_kernel(const float* __restrict__ Qs, const float* __restrict__ Kg,
                 const float* __restrict__ Vg, float* __restrict__ ctx,
                 float* __restrict__ meanv, int u)
{
    extern __shared__ float sm[];
    float* q    = sm;                      // 48*64
    float* KtT  = q + UMAX * 64;           // 64*KSTR
    float* Vt   = KtT + 64 * KSTR;         // TT*64
    float* P    = Vt + TT * 64;            // 48*TT
    float* msum = P + UMAX * TT;           // 64

    const int h = blockIdx.x, b = blockIdx.y;
    const int tid = threadIdx.x;
    const int wid = tid >> 5, lane = tid & 31;
    const int ur0 = wid * 6;

    for (int e = tid; e < UMAX * 64; e += 256) {
        int ur = e >> 6, c = e & 63;
        q[e] = (ur < u) ? Qs[(size_t)(b * u + ur) * D_ + h * 64 + c] * 0.125f : 0.f;
    }
    if (tid < 64) msum[tid] = 0.f;

    float m_run[6], l_run[6], acc_o[6][2];
#pragma unroll
    for (int i = 0; i < 6; i++) {
        m_run[i] = -1e30f; l_run[i] = 0.f;
        acc_o[i][0] = 0.f; acc_o[i][1] = 0.f;
    }
    __syncthreads();

    for (int t0 = 0; t0 < T_; t0 += TT) {
        for (int e = tid; e < TT * 16; e += 256) {
            int r = e >> 4, c4 = e & 15;
            size_t goff = (size_t)(b * T_ + t0 + r) * D_ + h * 64 + c4 * 4;
            float4 kv = *(const float4*)(Kg + goff);
            float4 vv = *(const float4*)(Vg + goff);
            KtT[(c4 * 4 + 0) * KSTR + r] = kv.x;
            KtT[(c4 * 4 + 1) * KSTR + r] = kv.y;
            KtT[(c4 * 4 + 2) * KSTR + r] = kv.z;
            KtT[(c4 * 4 + 3) * KSTR + r] = kv.w;
            *(float4*)(Vt + r * 64 + c4 * 4) = vv;
        }
        __syncthreads();

        float acc_s[6][4];
#pragma unroll
        for (int i = 0; i < 6; i++)
#pragma unroll
            for (int j = 0; j < 4; j++) acc_s[i][j] = 0.f;

        for (int c0 = 0; c0 < 64; c0 += 4) {
            float4 qv[6];
#pragma unroll
            for (int i = 0; i < 6; i++)
                qv[i] = *(const float4*)(q + (ur0 + i) * 64 + c0);
#pragma unroll
            for (int k = 0; k < 4; k++) {
                float4 kv = *(const float4*)(KtT + (c0 + k) * KSTR + lane * 4);
#pragma unroll
                for (int i = 0; i < 6; i++) {
                    float qs = (k == 0) ? qv[i].x : (k == 1) ? qv[i].y : (k == 2) ? qv[i].z : qv[i].w;
                    acc_s[i][0] += qs * kv.x;
                    acc_s[i][1] += qs * kv.y;
                    acc_s[i][2] += qs * kv.z;
                    acc_s[i][3] += qs * kv.w;
                }
            }
        }

#pragma unroll
        for (int i = 0; i < 6; i++) {
            float mx = fmaxf(fmaxf(acc_s[i][0], acc_s[i][1]), fmaxf(acc_s[i][2], acc_s[i][3]));
#pragma unroll
            for (int o = 16; o; o >>= 1) mx = fmaxf(mx, __shfl_xor_sync(0xffffffffu, mx, o));
            float mnew = fmaxf(m_run[i], mx);
            float corr = __expf(m_run[i] - mnew);
            float4 p;
            p.x = __expf(acc_s[i][0] - mnew);
            p.y = __expf(acc_s[i][1] - mnew);
            p.z = __expf(acc_s[i][2] - mnew);
            p.w = __expf(acc_s[i][3] - mnew);
            float ls = p.x + p.y + p.z + p.w;
#pragma unroll
            for (int o = 16; o; o >>= 1) ls += __shfl_xor_sync(0xffffffffu, ls, o);
            l_run[i] = l_run[i] * corr + ls;
            acc_o[i][0] *= corr;
            acc_o[i][1] *= corr;
            m_run[i] = mnew;
            *(float4*)(P + (ur0 + i) * TT + lane * 4) = p;
        }
        __syncwarp();

        for (int t4 = 0; t4 < TT; t4 += 4) {
            float4 pv[6];
#pragma unroll
            for (int i = 0; i < 6; i++)
                pv[i] = *(const float4*)(P + (ur0 + i) * TT + t4);
#pragma unroll
            for (int k = 0; k < 4; k++) {
                float v0 = Vt[(t4 + k) * 64 + lane];
                float v1 = Vt[(t4 + k) * 64 + lane + 32];
#pragma unroll
                for (int i = 0; i < 6; i++) {
                    float pp = (k == 0) ? pv[i].x : (k == 1) ? pv[i].y : (k == 2) ? pv[i].z : pv[i].w;
                    acc_o[i][0] += pp * v0;
                    acc_o[i][1] += pp * v1;
                }
            }
        }
        __syncthreads();
    }

#pragma unroll
    for (int i = 0; i < 6; i++) {
        int urg = ur0 + i;
        if (urg < u) {
            float inv = 1.f / l_run[i];
            float o0 = acc_o[i][0] * inv;
            float o1 = acc_o[i][1] * inv;
            size_t base = (size_t)(b * u + urg) * D_ + h * 64;
            ctx[base + lane]      = o0;
            ctx[base + lane + 32] = o1;
            atomicAdd(&msum[lane],      o0);
            atomicAdd(&msum[lane + 32], o1);
        }
    }
    __syncthreads();
    if (tid < 64) meanv[b * D_ + h * 64 + tid] = msum[tid] / (float)u;
}

// ---------------------------------------------------------------------------
__global__ void broadcast_out(const float* __restrict__ yo_mean, float* __restrict__ out)
{
    size_t i = (size_t)blockIdx.x * blockDim.x + threadIdx.x;
    if (i >= (size_t)B_ * T_ * (D_ / 4)) return;
    int d4 = (int)(i & (D_ / 4 - 1));
    int b  = (int)(i >> 8) >> 12;
    ((float4*)out)[i] = ((const float4*)yo_mean)[b * (D_ / 4) + d4];
}

__global__ void scatter_out(const float* __restrict__ yo_idx, const int* __restrict__ idx,
                            float* __restrict__ out, int u)
{
    int row = blockIdx.x;
    int b = row / u, iu = row - b * u;
    int t = idx[iu];
    const float4* src = (const float4*)(yo_idx + (size_t)row * D_);
    float4* dst = (float4*)(out + ((size_t)(b * T_ + t)) * D_);
    dst[threadIdx.x] = src[threadIdx.x];
}

// ---------------------------------------------------------------------------
// Launch
// ---------------------------------------------------------------------------
extern "C" void kernel_launch(void* const* d_in, const int* in_sizes, int n_in,
                              void* d_out, int out_size)
{
    const float* x  = (const float*)d_in[0];
    const float* Wq = (const float*)d_in[1];
    const float* Wk = (const float*)d_in[2];
    const float* Wv = (const float*)d_in[3];
    const float* Wo = (const float*)d_in[4];
    const float* bo = (const float*)d_in[5];
    const int*  idx = (const int*)d_in[6];
    const int u = in_sizes[6];
    float* out = (float*)d_out;

    float *pK, *pV, *pQs, *pctx, *pmean, *pyom, *pyoi;
    int* prm;
    __half *pXh, *pXl, *pWkh, *pWvh;
    cudaGetSymbolAddress((void**)&pK,    g_K);
    cudaGetSymbolAddress((void**)&pV,    g_V);
    cudaGetSymbolAddress((void**)&pQs,   g_Qs);
    cudaGetSymbolAddress((void**)&pctx,  g_ctx);
    cudaGetSymbolAddress((void**)&pmean, g_mean);
    cudaGetSymbolAddress((void**)&pyom,  g_yo_mean);
    cudaGetSymbolAddress((void**)&pyoi,  g_yo_idx);
    cudaGetSymbolAddress((void**)&prm,   g_rowmap);
    cudaGetSymbolAddress((void**)&pXh,   g_Xh);
    cudaGetSymbolAddress((void**)&pXl,   g_Xl);
    cudaGetSymbolAddress((void**)&pWkh,  g_Wkh);
    cudaGetSymbolAddress((void**)&pWvh,  g_Wvh);

    // 0. fp16 preps
    {
        int n4x = (B_ * T_ * D_) / 4;
        split_f16_hl<<<(n4x + 255) / 256, 256>>>(x, pXh, pXl, n4x);
        int n4w = (D_ * D_) / 4;
        conv_f16<<<(n4w + 255) / 256, 256>>>(Wk, pWkh, n4w);
        conv_f16<<<(n4w + 255) / 256, 256>>>(Wv, pWvh, n4w);
    }

    // 1. gather map for query rows
    build_rowmap<<<(B_ * u + 255) / 256, 256>>>(idx, prm, u);

    // 2. Qs = x[idx] @ Wq^T (small, fp32 SIMT)
    gemm_xwT<<<dim3(D_ / BN, (B_ * u + BM - 1) / BM), 256>>>(x, Wq, pQs, prm, nullptr, B_ * u);

    // 3. fused K+V projection — HMMA fp16 2-term
    cudaFuncSetAttribute((const void*)gemm_fused,
                         cudaFuncAttributeMaxDynamicSharedMemorySize, GEMM_SMEM);
    dim3 gkv(D_ / 128, (B_ * T_) / 128);
    gemm_fused<<<gkv, 512, GEMM_SMEM>>>(pXh, pXl, pWkh, pWvh, pK, pV);

    // 4. flash attention per (b,h) — register-tiled
    const size_t smem_bytes = sizeof(float) *
        (UMAX * 64 + 64 * KSTR + TT * 64 + UMAX * TT + 64);
    cudaFuncSetAttribute((const void*)attn_kernel,
                         cudaFuncAttributeMaxDynamicSharedMemorySize, (int)smem_bytes);
    attn_kernel<<<dim3(H_, B_), 256, smem_bytes>>>(pQs, pK, pV, pctx, pmean, u);

    // 5. epilogue: rows through Wo (+bo)
    gemm_xwT<<<dim3(D_ / BN, (B_ * u + BM - 1) / BM), 256>>>(pctx, Wo, pyoi, nullptr, bo, B_ * u);
    gemm_xwT<<<dim3(D_ / BN, 1), 256>>>(pmean, Wo, pyom, nullptr, bo, B_);

    // 6. broadcast mean row everywhere, then overwrite idx rows
    size_t nvec = (size_t)B_ * T_ * (D_ / 4);
    broadcast_out<<<(unsigned)((nvec + 255) / 256), 256>>>(pyom, out);
    scatter_out<<<B_ * u, 256>>>(pyoi, idx, out, u);
}

// round 6
// speedup vs baseline: 3.8348x; 1.3715x over previous
#include <cuda_runtime.h>
#include <cuda_fp16.h>
#include <cstdint>

// Problem constants (fixed by the dataset)
#define B_  8
#define T_  4096
#define D_  1024
#define H_  16
#define DH_ 64
#define UMAX 48      // u = 41 actual; attention pads to 48 (8 warps x 6 rows)
#define TT  128      // attention K/V tile (time dimension)

// ---------------------------------------------------------------------------
// Scratch (device globals — no allocations allowed)
// ---------------------------------------------------------------------------
__device__ float g_K[(size_t)B_ * T_ * D_];        // 134 MB
__device__ float g_V[(size_t)B_ * T_ * D_];        // 134 MB
__device__ float g_Qs[B_ * UMAX * D_];
__device__ float g_ctx[B_ * UMAX * D_];
__device__ float g_mean[B_ * D_];
__device__ float g_yo_mean[B_ * D_];
__device__ float g_yo_idx[B_ * UMAX * D_];
__device__ int   g_rowmap[B_ * UMAX];

// fp16 planes for tensor-core GEMMs
__device__ __half g_Xh[(size_t)B_ * T_ * D_];      // 64 MB
__device__ __half g_Xl[(size_t)B_ * T_ * D_];      // 64 MB
__device__ __half g_Wkh[D_ * D_];
__device__ __half g_Wvh[D_ * D_];
__device__ __half g_Wqh[D_ * D_];
__device__ __half g_Woh[D_ * D_];
__device__ __half g_ctxh[B_ * UMAX * D_];
__device__ __half g_ctxl[B_ * UMAX * D_];

// ---------------------------------------------------------------------------
// PTX helpers (sm_80+ portable: mma.sync + ldmatrix + cp.async)
// ---------------------------------------------------------------------------
__device__ __forceinline__ uint32_t smem_u32(const void* p) {
    uint32_t a;
    asm("{ .reg .u64 t; cvta.to.shared.u64 t, %1; cvt.u32.u64 %0, t; }" : "=r"(a) : "l"(p));
    return a;
}
__device__ __forceinline__ void cp16(uint32_t sdst, const void* gsrc) {
    asm volatile("cp.async.cg.shared.global [%0], [%1], 16;" :: "r"(sdst), "l"(gsrc));
}
#define CP_COMMIT() asm volatile("cp.async.commit_group;" ::: "memory")
#define CP_WAIT1()  asm volatile("cp.async.wait_group 1;" ::: "memory")

__device__ __forceinline__ void ldsm_x4(uint32_t* r, uint32_t addr) {
    asm volatile("ldmatrix.sync.aligned.m8n8.x4.shared.b16 {%0,%1,%2,%3}, [%4];"
        : "=r"(r[0]), "=r"(r[1]), "=r"(r[2]), "=r"(r[3]) : "r"(addr));
}
__device__ __forceinline__ void mma16816f16(float* c, const uint32_t* a, const uint32_t* b) {
    asm volatile(
        "mma.sync.aligned.m16n8k16.row.col.f32.f16.f16.f32 "
        "{%0,%1,%2,%3}, {%4,%5,%6,%7}, {%8,%9}, {%0,%1,%2,%3};"
        : "+f"(c[0]), "+f"(c[1]), "+f"(c[2]), "+f"(c[3])
        : "r"(a[0]), "r"(a[1]), "r"(a[2]), "r"(a[3]), "r"(b[0]), "r"(b[1]));
}

// ---------------------------------------------------------------------------
// prep kernels: fp16 hi/lo split, fp16 convert
// ---------------------------------------------------------------------------
__global__ void split_f16_hl(const float* __restrict__ src,
                             __half* __restrict__ hi, __half* __restrict__ lo, int n4)
{
    int i = blockIdx.x * blockDim.x + threadIdx.x;
    if (i >= n4) return;
    float4 v = ((const float4*)src)[i];
    __half h0 = __float2half(v.x), h1 = __float2half(v.y);
    __half h2 = __float2half(v.z), h3 = __float2half(v.w);
    __half l0 = __float2half(v.x - __half2float(h0));
    __half l1 = __float2half(v.y - __half2float(h1));
    __half l2 = __float2half(v.z - __half2float(h2));
    __half l3 = __float2half(v.w - __half2float(h3));
    ((__half2*)hi)[2 * i]     = __halves2half2(h0, h1);
    ((__half2*)hi)[2 * i + 1] = __halves2half2(h2, h3);
    ((__half2*)lo)[2 * i]     = __halves2half2(l0, l1);
    ((__half2*)lo)[2 * i + 1] = __halves2half2(l2, l3);
}

__global__ void conv_f16(const float* __restrict__ src, __half* __restrict__ dst, int n4)
{
    int i = blockIdx.x * blockDim.x + threadIdx.x;
    if (i >= n4) return;
    float4 v = ((const float4*)src)[i];
    ((__half2*)dst)[2 * i]     = __halves2half2(__float2half(v.x), __float2half(v.y));
    ((__half2*)dst)[2 * i + 1] = __halves2half2(__float2half(v.z), __float2half(v.w));
}

// ---------------------------------------------------------------------------
// Fused K+V tensor-core GEMM (fp16 2-term). 512 threads: warps 0-7 -> K,
// warps 8-15 -> V (shared A stages). BM=BN=128, BK=32, double-buffered.
// ---------------------------------------------------------------------------
#define PSTR  40                 // padded row stride in f16 elems (80 B)
#define MATB  (128 * 80)         // 10240 B per matrix
#define STG   (4 * MATB)         // 40960 B per stage
#define GEMM_SMEM (2 * STG)

__device__ __forceinline__ void load_stage(
    uint32_t sdst,
    const __half* __restrict__ Xh, const __half* __restrict__ Xl,
    const __half* __restrict__ Bk, const __half* __restrict__ Bv,
    int bm, int bn, int k0, int tid)
{
#pragma unroll
    for (int m = 0; m < 4; m++) {
        const __half* base = (m == 0) ? Xh : (m == 1) ? Xl : (m == 2) ? Bk : Bv;
        int rowbase = (m < 2) ? bm : bn;
        int c = tid;
        int row = c >> 2, c16 = c & 3;
        const __half* src = base + ((size_t)(rowbase + row) << 10) + k0 + c16 * 8;
        uint32_t dst = sdst + m * MATB + row * 80 + c16 * 16;
        cp16(dst, src);
    }
}

__global__ __launch_bounds__(512, 1)
void gemm_fused(const __half* __restrict__ Xh, const __half* __restrict__ Xl,
                const __half* __restrict__ Bk, const __half* __restrict__ Bv,
                float* __restrict__ Ck, float* __restrict__ Cv)
{
    extern __shared__ char smem[];
    const uint32_t sb = smem_u32(smem);
    const int tid = threadIdx.x;
    const int wid = tid >> 5, lane = tid & 31;
    const int isV = wid >> 3;
    const int ww  = wid & 7;
    const int bm = blockIdx.y * 128;
    const int bn = blockIdx.x * 128;
    const int wm = (ww >> 2) * 64;
    const int wn = (ww & 3) * 32;

    float acc[4][4][4];
#pragma unroll
    for (int mi = 0; mi < 4; mi++)
#pragma unroll
        for (int ni = 0; ni < 4; ni++)
#pragma unroll
            for (int r = 0; r < 4; r++) acc[mi][ni][r] = 0.f;

    load_stage(sb,       Xh, Xl, Bk, Bv, bm, bn, 0,  tid); CP_COMMIT();
    load_stage(sb + STG, Xh, Xl, Bk, Bv, bm, bn, 32, tid); CP_COMMIT();

    const int l16 = lane & 15;
    const int arow = l16;
    const int acolb = (lane >> 4) * 8;
    const int bg = lane >> 3;
    const int brow8 = lane & 7;
    const uint32_t boff = (2 + isV) * MATB;

    for (int kt = 0; kt < 32; kt++) {
        uint32_t ss = sb + (kt & 1) * STG;
        CP_WAIT1();
        __syncthreads();

#pragma unroll
        for (int ks = 0; ks < 2; ks++) {
            uint32_t ah[4][4], al[4][4], b[4][2];
            const int acol = acolb + ks * 16;
#pragma unroll
            for (int mi = 0; mi < 4; mi++) {
                uint32_t ao = ss + ((wm + mi * 16 + arow) * PSTR + acol) * 2;
                ldsm_x4(ah[mi], ao);
                ldsm_x4(al[mi], ao + MATB);
            }
#pragma unroll
            for (int nip = 0; nip < 2; nip++) {
                int brr = wn + (2 * nip + (bg >> 1)) * 8 + brow8;
                int bcc = (bg & 1) * 8 + ks * 16;
                uint32_t r4[4];
                ldsm_x4(r4, ss + boff + (brr * PSTR + bcc) * 2);
                b[2 * nip][0] = r4[0]; b[2 * nip][1] = r4[1];
                b[2 * nip + 1][0] = r4[2]; b[2 * nip + 1][1] = r4[3];
            }
#pragma unroll
            for (int mi = 0; mi < 4; mi++)
#pragma unroll
                for (int ni = 0; ni < 4; ni++) {
                    mma16816f16(acc[mi][ni], ah[mi], b[ni]);
                    mma16816f16(acc[mi][ni], al[mi], b[ni]);
                }
        }
        __syncthreads();
        if (kt + 2 < 32)
            load_stage(ss, Xh, Xl, Bk, Bv, bm, bn, (kt + 2) * 32, tid);
        CP_COMMIT();
    }

    float* C = isV ? Cv : Ck;
    const int r0 = lane >> 2, c0 = (lane & 3) * 2;
#pragma unroll
    for (int mi = 0; mi < 4; mi++)
#pragma unroll
        for (int ni = 0; ni < 4; ni++) {
            int gr = bm + wm + mi * 16 + r0;
            int gc = bn + wn + ni * 8 + c0;
            float2 v0; v0.x = acc[mi][ni][0]; v0.y = acc[mi][ni][1];
            float2 v1; v1.x = acc[mi][ni][2]; v1.y = acc[mi][ni][3];
            *(float2*)(C + (size_t)gr * D_ + gc) = v0;
            *(float2*)(C + (size_t)(gr + 8) * D_ + gc) = v1;
        }
}

// ---------------------------------------------------------------------------
// Small-M HMMA GEMM (fp16 2-term A): C[m,n] = sum_k (Ah+Al)[row(m),k]*B[n,k] (+bias)
// BM=64, BN=128, BK=32, 256 threads (8 warps: 2x4 of 32x32 warp tiles).
// Stage (20480 B): Ah(5120) | Al(5120) | B(10240).
// ---------------------------------------------------------------------------
#define SMATA (64 * 80)          // 5120
#define SMATB (128 * 80)         // 10240
#define SSTG  (2 * SMATA + SMATB) // 20480
#define SMALL_SMEM (2 * SSTG)

__device__ __forceinline__ void load_stage_small(
    uint32_t sdst,
    const __half* __restrict__ Ah, const __half* __restrict__ Al,
    const __half* __restrict__ Bm, const int* __restrict__ rowmap,
    int bm, int bn, int k0, int tid, int M)
{
    {
        int row = tid >> 2, c16 = tid & 3;
        int gm = bm + row;
        int sr = (gm < M) ? gm : (M - 1);
        if (rowmap) sr = rowmap[sr];
        uint32_t d = sdst + row * 80 + c16 * 16;
        cp16(d,         Ah + ((size_t)sr << 10) + k0 + c16 * 8);
        cp16(d + SMATA, Al + ((size_t)sr << 10) + k0 + c16 * 8);
    }
#pragma unroll
    for (int j = 0; j < 2; j++) {
        int c = tid + j * 256;
        int row = c >> 2, c16 = c & 3;
        cp16(sdst + 2 * SMATA + row * 80 + c16 * 16,
             Bm + ((size_t)(bn + row) << 10) + k0 + c16 * 8);
    }
}

__global__ __launch_bounds__(256)
void gemm_small(const __half* __restrict__ Ah, const __half* __restrict__ Al,
                const __half* __restrict__ Bm, float* __restrict__ C,
                const int* __restrict__ rowmap, const float* __restrict__ bias, int M)
{
    extern __shared__ char smem[];
    const uint32_t sb = smem_u32(smem);
    const int tid = threadIdx.x;
    const int wid = tid >> 5, lane = tid & 31;
    const int bm = blockIdx.y * 64;
    const int bn = blockIdx.x * 128;
    const int wm = (wid >> 2) * 32;
    const int wn = (wid & 3) * 32;

    float acc[2][4][4];
#pragma unroll
    for (int mi = 0; mi < 2; mi++)
#pragma unroll
        for (int ni = 0; ni < 4; ni++)
#pragma unroll
            for (int r = 0; r < 4; r++) acc[mi][ni][r] = 0.f;

    load_stage_small(sb,        Ah, Al, Bm, rowmap, bm, bn, 0,  tid, M); CP_COMMIT();
    load_stage_small(sb + SSTG, Ah, Al, Bm, rowmap, bm, bn, 32, tid, M); CP_COMMIT();

    const int l16 = lane & 15;
    const int arow = l16;
    const int acolb = (lane >> 4) * 8;
    const int bg = lane >> 3;
    const int brow8 = lane & 7;

    for (int kt = 0; kt < 32; kt++) {
        uint32_t ss = sb + (kt & 1) * SSTG;
        CP_WAIT1();
        __syncthreads();

#pragma unroll
        for (int ks = 0; ks < 2; ks++) {
            uint32_t ah[2][4], al[2][4], b[4][2];
            const int acol = acolb + ks * 16;
#pragma unroll
            for (int mi = 0; mi < 2; mi++) {
                uint32_t ao = ss + ((wm + mi * 16 + arow) * PSTR + acol) * 2;
                ldsm_x4(ah[mi], ao);
                ldsm_x4(al[mi], ao + SMATA);
            }
#pragma unroll
            for (int nip = 0; nip < 2; nip++) {
                int brr = wn + (2 * nip + (bg >> 1)) * 8 + brow8;
                int bcc = (bg & 1) * 8 + ks * 16;
                uint32_t r4[4];
                ldsm_x4(r4, ss + 2 * SMATA + (brr * PSTR + bcc) * 2);
                b[2 * nip][0] = r4[0]; b[2 * nip][1] = r4[1];
                b[2 * nip + 1][0] = r4[2]; b[2 * nip + 1][1] = r4[3];
            }
#pragma unroll
            for (int mi = 0; mi < 2; mi++)
#pragma unroll
                for (int ni = 0; ni < 4; ni++) {
                    mma16816f16(acc[mi][ni], ah[mi], b[ni]);
                    mma16816f16(acc[mi][ni], al[mi], b[ni]);
                }
        }
        __syncthreads();
        if (kt + 2 < 32)
            load_stage_small(ss, Ah, Al, Bm, rowmap, bm, bn, (kt + 2) * 32, tid, M);
        CP_COMMIT();
    }

    const int r0 = lane >> 2, c0 = (lane & 3) * 2;
#pragma unroll
    for (int mi = 0; mi < 2; mi++)
#pragma unroll
        for (int ni = 0; ni < 4; ni++) {
            int gr = bm + wm + mi * 16 + r0;
            int gc = bn + wn + ni * 8 + c0;
            float b0 = bias ? bias[gc] : 0.f;
            float b1 = bias ? bias[gc + 1] : 0.f;
            if (gr < M) {
                float2 v; v.x = acc[mi][ni][0] + b0; v.y = acc[mi][ni][1] + b1;
                *(float2*)(C + (size_t)gr * D_ + gc) = v;
            }
            if (gr + 8 < M) {
                float2 v; v.x = acc[mi][ni][2] + b0; v.y = acc[mi][ni][3] + b1;
                *(float2*)(C + (size_t)(gr + 8) * D_ + gc) = v;
            }
        }
}

// ---------------------------------------------------------------------------
// mean @ Wo^T GEMV (fp32): yo_mean[b][n] = dot(mean[b], Wo[n]) + bo[n]
// 128 blocks x 256 threads; warp per output col (8 cols/block), mean in smem.
// ---------------------------------------------------------------------------
__global__ __launch_bounds__(256)
void gemv_mean(const float* __restrict__ meanv, const float* __restrict__ Wo,
               const float* __restrict__ bo, float* __restrict__ yo_mean)
{
    __shared__ float smean[B_ * D_ / 128];   // not used; see below
    (void)smean;
    const int tid = threadIdx.x;
    const int wid = tid >> 5, lane = tid & 31;
    const int n = blockIdx.x * 8 + wid;

    float acc[B_];
#pragma unroll
    for (int b = 0; b < B_; b++) acc[b] = 0.f;

    const float4* wrow = (const float4*)(Wo + (size_t)n * D_);
    for (int k4 = lane; k4 < D_ / 4; k4 += 32) {
        float4 w = wrow[k4];
#pragma unroll
        for (int b = 0; b < B_; b++) {
            float4 m = *(const float4*)(meanv + b * D_ + k4 * 4);
            acc[b] += w.x * m.x + w.y * m.y + w.z * m.z + w.w * m.w;
        }
    }
#pragma unroll
    for (int b = 0; b < B_; b++) {
#pragma unroll
        for (int o = 16; o; o >>= 1) acc[b] += __shfl_xor_sync(0xffffffffu, acc[b], o);
    }
    if (lane == 0) {
        float bb = bo[n];
#pragma unroll
        for (int b = 0; b < B_; b++) yo_mean[b * D_ + n] = acc[b] + bb;
    }
}

// ---------------------------------------------------------------------------
__global__ void build_rowmap(const int* __restrict__ idx, int* __restrict__ rowmap, int u)
{
    int i = blockIdx.x * blockDim.x + threadIdx.x;
    if (i < B_ * u) {
        int b = i / u, iu = i - b * u;
        rowmap[i] = b * T_ + idx[iu];
    }
}

// ---------------------------------------------------------------------------
// Flash attention, register-tiled. One CTA per (b,h); 8 warps x 6 query rows.
// ---------------------------------------------------------------------------
#define KSTR 132

__global__ __launch_bounds__(256)
void attn_kernel(const float* __restrict__ Qs, const float* __restrict__ Kg,
                 const float* __restrict__ Vg, float* __restrict__ ctx,
                 float* __restrict__ meanv, int u)
{
    extern __shared__ float sm[];
    float* q    = sm;                      // 48*64
    float* KtT  = q + UMAX * 64;           // 64*KSTR
    float* Vt   = KtT + 64 * KSTR;         // TT*64
    float* P    = Vt + TT * 64;            // 48*TT
    float* msum = P + UMAX * TT;           // 64

    const int h = blockIdx.x, b = blockIdx.y;
    const int tid = threadIdx.x;
    const int wid = tid >> 5, lane = tid & 31;
    const int ur0 = wid * 6;

    for (int e = tid; e < UMAX * 64; e += 256) {
        int ur = e >> 6, c = e & 63;
        q[e] = (ur < u) ? Qs[(size_t)(b * u + ur) * D_ + h * 64 + c] * 0.125f : 0.f;
    }
    if (tid < 64) msum[tid] = 0.f;

    float m_run[6], l_run[6], acc_o[6][2];
#pragma unroll
    for (int i = 0; i < 6; i++) {
        m_run[i] = -1e30f; l_run[i] = 0.f;
        acc_o[i][0] = 0.f; acc_o[i][1] = 0.f;
    }
    __syncthreads();

    for (int t0 = 0; t0 < T_; t0 += TT) {
        for (int e = tid; e < TT * 16; e += 256) {
            int r = e >> 4, c4 = e & 15;
            size_t goff = (size_t)(b * T_ + t0 + r) * D_ + h * 64 + c4 * 4;
            float4 kv = *(const float4*)(Kg + goff);
            float4 vv = *(const float4*)(Vg + goff);
            KtT[(c4 * 4 + 0) * KSTR + r] = kv.x;
            KtT[(c4 * 4 + 1) * KSTR + r] = kv.y;
            KtT[(c4 * 4 + 2) * KSTR + r] = kv.z;
            KtT[(c4 * 4 + 3) * KSTR + r] = kv.w;
            *(float4*)(Vt + r * 64 + c4 * 4) = vv;
        }
        __syncthreads();

        float acc_s[6][4];
#pragma unroll
        for (int i = 0; i < 6; i++)
#pragma unroll
            for (int j = 0; j < 4; j++) acc_s[i][j] = 0.f;

        for (int c0 = 0; c0 < 64; c0 += 4) {
            float4 qv[6];
#pragma unroll
            for (int i = 0; i < 6; i++)
                qv[i] = *(const float4*)(q + (ur0 + i) * 64 + c0);
#pragma unroll
            for (int k = 0; k < 4; k++) {
                float4 kv = *(const float4*)(KtT + (c0 + k) * KSTR + lane * 4);
#pragma unroll
                for (int i = 0; i < 6; i++) {
                    float qs = (k == 0) ? qv[i].x : (k == 1) ? qv[i].y : (k == 2) ? qv[i].z : qv[i].w;
                    acc_s[i][0] += qs * kv.x;
                    acc_s[i][1] += qs * kv.y;
                    acc_s[i][2] += qs * kv.z;
                    acc_s[i][3] += qs * kv.w;
                }
            }
        }

#pragma unroll
        for (int i = 0; i < 6; i++) {
            float mx = fmaxf(fmaxf(acc_s[i][0], acc_s[i][1]), fmaxf(acc_s[i][2], acc_s[i][3]));
#pragma unroll
            for (int o = 16; o; o >>= 1) mx = fmaxf(mx, __shfl_xor_sync(0xffffffffu, mx, o));
            float mnew = fmaxf(m_run[i], mx);
            float corr = __expf(m_run[i] - mnew);
            float4 p;
            p.x = __expf(acc_s[i][0] - mnew);
            p.y = __expf(acc_s[i][1] - mnew);
            p.z = __expf(acc_s[i][2] - mnew);
            p.w = __expf(acc_s[i][3] - mnew);
            float ls = p.x + p.y + p.z + p.w;
#pragma unroll
            for (int o = 16; o; o >>= 1) ls += __shfl_xor_sync(0xffffffffu, ls, o);
            l_run[i] = l_run[i] * corr + ls;
            acc_o[i][0] *= corr;
            acc_o[i][1] *= corr;
            m_run[i] = mnew;
            *(float4*)(P + (ur0 + i) * TT + lane * 4) = p;
        }
        __syncwarp();

        for (int t4 = 0; t4 < TT; t4 += 4) {
            float4 pv[6];
#pragma unroll
            for (int i = 0; i < 6; i++)
                pv[i] = *(const float4*)(P + (ur0 + i) * TT + t4);
#pragma unroll
            for (int k = 0; k < 4; k++) {
                float v0 = Vt[(t4 + k) * 64 + lane];
                float v1 = Vt[(t4 + k) * 64 + lane + 32];
#pragma unroll
                for (int i = 0; i < 6; i++) {
                    float pp = (k == 0) ? pv[i].x : (k == 1) ? pv[i].y : (k == 2) ? pv[i].z : pv[i].w;
                    acc_o[i][0] += pp * v0;
                    acc_o[i][1] += pp * v1;
                }
            }
        }
        __syncthreads();
    }

#pragma unroll
    for (int i = 0; i < 6; i++) {
        int urg = ur0 + i;
        if (urg < u) {
            float inv = 1.f / l_run[i];
            float o0 = acc_o[i][0] * inv;
            float o1 = acc_o[i][1] * inv;
            size_t base = (size_t)(b * u + urg) * D_ + h * 64;
            ctx[base + lane]      = o0;
            ctx[base + lane + 32] = o1;
            atomicAdd(&msum[lane],      o0);
            atomicAdd(&msum[lane + 32], o1);
        }
    }
    __syncthreads();
    if (tid < 64) meanv[b * D_ + h * 64 + tid] = msum[tid] / (float)u;
}

// ---------------------------------------------------------------------------
__global__ void broadcast_out(const float* __restrict__ yo_mean, float* __restrict__ out)
{
    size_t i = (size_t)blockIdx.x * blockDim.x + threadIdx.x;
    if (i >= (size_t)B_ * T_ * (D_ / 4)) return;
    int d4 = (int)(i & (D_ / 4 - 1));
    int b  = (int)(i >> 20);
    ((float4*)out)[i] = ((const float4*)yo_mean)[b * (D_ / 4) + d4];
}

__global__ void scatter_out(const float* __restrict__ yo_idx, const int* __restrict__ idx,
                            float* __restrict__ out, int u)
{
    int row = blockIdx.x;
    int b = row / u, iu = row - b * u;
    int t = idx[iu];
    const float4* src = (const float4*)(yo_idx + (size_t)row * D_);
    float4* dst = (float4*)(out + ((size_t)(b * T_ + t)) * D_);
    dst[threadIdx.x] = src[threadIdx.x];
}

// ---------------------------------------------------------------------------
// Launch
// ---------------------------------------------------------------------------
extern "C" void kernel_launch(void* const* d_in, const int* in_sizes, int n_in,
                              void* d_out, int out_size)
{
    const float* x  = (const float*)d_in[0];
    const float* Wq = (const float*)d_in[1];
    const float* Wk = (const float*)d_in[2];
    const float* Wv = (const float*)d_in[3];
    const float* Wo = (const float*)d_in[4];
    const float* bo = (const float*)d_in[5];
    const int*  idx = (const int*)d_in[6];
    const int u = in_sizes[6];
    float* out = (float*)d_out;

    float *pK, *pV, *pQs, *pctx, *pmean, *pyom, *pyoi;
    int* prm;
    __half *pXh, *pXl, *pWkh, *pWvh, *pWqh, *pWoh, *pCh, *pCl;
    cudaGetSymbolAddress((void**)&pK,    g_K);
    cudaGetSymbolAddress((void**)&pV,    g_V);
    cudaGetSymbolAddress((void**)&pQs,   g_Qs);
    cudaGetSymbolAddress((void**)&pctx,  g_ctx);
    cudaGetSymbolAddress((void**)&pmean, g_mean);
    cudaGetSymbolAddress((void**)&pyom,  g_yo_mean);
    cudaGetSymbolAddress((void**)&pyoi,  g_yo_idx);
    cudaGetSymbolAddress((void**)&prm,   g_rowmap);
    cudaGetSymbolAddress((void**)&pXh,   g_Xh);
    cudaGetSymbolAddress((void**)&pXl,   g_Xl);
    cudaGetSymbolAddress((void**)&pWkh,  g_Wkh);
    cudaGetSymbolAddress((void**)&pWvh,  g_Wvh);
    cudaGetSymbolAddress((void**)&pWqh,  g_Wqh);
    cudaGetSymbolAddress((void**)&pWoh,  g_Woh);
    cudaGetSymbolAddress((void**)&pCh,   g_ctxh);
    cudaGetSymbolAddress((void**)&pCl,   g_ctxl);

    const int M = B_ * u;   // 328

    // 0. fp16 preps
    {
        int n4x = (B_ * T_ * D_) / 4;
        split_f16_hl<<<(n4x + 255) / 256, 256>>>(x, pXh, pXl, n4x);
        int n4w = (D_ * D_) / 4;
        conv_f16<<<(n4w + 255) / 256, 256>>>(Wk, pWkh, n4w);
        conv_f16<<<(n4w + 255) / 256, 256>>>(Wv, pWvh, n4w);
        conv_f16<<<(n4w + 255) / 256, 256>>>(Wq, pWqh, n4w);
        conv_f16<<<(n4w + 255) / 256, 256>>>(Wo, pWoh, n4w);
    }

    // 1. gather map for query rows
    build_rowmap<<<(B_ * u + 255) / 256, 256>>>(idx, prm, u);

    // 2. Qs = x[idx] @ Wq^T — HMMA small GEMM with gather
    cudaFuncSetAttribute((const void*)gemm_small,
                         cudaFuncAttributeMaxDynamicSharedMemorySize, SMALL_SMEM);
    dim3 gq(D_ / 128, (M + 63) / 64);
    gemm_small<<<gq, 256, SMALL_SMEM>>>(pXh, pXl, pWqh, pQs, prm, nullptr, M);

    // 3. fused K+V projection — HMMA fp16 2-term
    cudaFuncSetAttribute((const void*)gemm_fused,
                         cudaFuncAttributeMaxDynamicSharedMemorySize, GEMM_SMEM);
    dim3 gkv(D_ / 128, (B_ * T_) / 128);
    gemm_fused<<<gkv, 512, GEMM_SMEM>>>(pXh, pXl, pWkh, pWvh, pK, pV);

    // 4. flash attention per (b,h) — register-tiled
    const size_t smem_bytes = sizeof(float) *
        (UMAX * 64 + 64 * KSTR + TT * 64 + UMAX * TT + 64);
    cudaFuncSetAttribute((const void*)attn_kernel,
                         cudaFuncAttributeMaxDynamicSharedMemorySize, (int)smem_bytes);
    attn_kernel<<<dim3(H_, B_), 256, smem_bytes>>>(pQs, pK, pV, pctx, pmean, u);

    // 5. epilogue idx rows: split ctx, then HMMA small GEMM with bias
    {
        int n4c = (M * D_) / 4;
        split_f16_hl<<<(n4c + 255) / 256, 256>>>(pctx, pCh, pCl, n4c);
        gemm_small<<<gq, 256, SMALL_SMEM>>>(pCh, pCl, pWoh, pyoi, nullptr, bo, M);
    }

    // 6. mean row through Wo — fp32 GEMV
    gemv_mean<<<D_ / 8, 256>>>(pmean, Wo, bo, pyom);

    // 7. broadcast mean row everywhere, then overwrite idx rows
    size_t nvec = (size_t)B_ * T_ * (D_ / 4);
    broadcast_out<<<(unsigned)((nvec + 255) / 256), 256>>>(pyom, out);
    scatter_out<<<B_ * u, 256>>>(pyoi, idx, out, u);
}